// round 4
// baseline (speedup 1.0000x reference)
#include <cuda_runtime.h>
#include <cuda_bf16.h>
#include <math.h>
#include <stdint.h>

// ---------------- problem constants ----------------
#define BB    2
#define TT    2048
#define HID   4096
#define NH    32
#define NKV   8
#define HD    128
#define MROWS (BB*TT)      // 4096
#define NQ    (NH*HD)      // 4096
#define NKVD  (NKV*HD)     // 1024
#define GROUPS (NH/NKV)    // 4

// ---------------- scratch (device globals, no allocation) ----------------
__device__ __nv_bfloat16 g_xh[(size_t)MROWS * HID];
__device__ __nv_bfloat16 g_xl[(size_t)MROWS * HID];
__device__ __nv_bfloat16 g_wqt_h[(size_t)NQ * HID],   g_wqt_l[(size_t)NQ * HID];
__device__ __nv_bfloat16 g_wkt_h[(size_t)NKVD * HID], g_wkt_l[(size_t)NKVD * HID];
__device__ __nv_bfloat16 g_wvt_h[(size_t)NKVD * HID], g_wvt_l[(size_t)NKVD * HID];
__device__ __nv_bfloat16 g_wot_h[(size_t)HID * NQ],   g_wot_l[(size_t)HID * NQ];
__device__ __nv_bfloat16 g_ah[(size_t)MROWS * NQ],    g_al[(size_t)MROWS * NQ];
__device__ float g_q[(size_t)MROWS * NQ];
__device__ float g_k[(size_t)MROWS * NKVD];
__device__ float g_v[(size_t)MROWS * NKVD];
__device__ float g_attn[(size_t)MROWS * NQ];

// ---------------- PTX helpers (base ISA only) ----------------
__device__ __forceinline__ uint32_t smem_u32(const void* p) {
    uint32_t a;
    asm("{ .reg .u64 t; cvta.to.shared.u64 t, %1; cvt.u32.u64 %0, t; }" : "=r"(a) : "l"(p));
    return a;
}

__device__ __forceinline__ void cp16(uint32_t dst, const void* src) {
    asm volatile("cp.async.cg.shared.global [%0], [%1], 16;" :: "r"(dst), "l"(src));
}

__device__ __forceinline__ void ldsm_x4(uint32_t* r, uint32_t addr) {
    asm volatile("ldmatrix.sync.aligned.m8n8.x4.shared.b16 {%0,%1,%2,%3}, [%4];"
                 : "=r"(r[0]), "=r"(r[1]), "=r"(r[2]), "=r"(r[3]) : "r"(addr));
}

__device__ __forceinline__ void mma16816(float* d, const uint32_t* a, const uint32_t* b) {
    asm volatile(
        "mma.sync.aligned.m16n8k16.row.col.f32.bf16.bf16.f32 "
        "{%0,%1,%2,%3}, {%4,%5,%6,%7}, {%8,%9}, {%0,%1,%2,%3};"
        : "+f"(d[0]), "+f"(d[1]), "+f"(d[2]), "+f"(d[3])
        : "r"(a[0]), "r"(a[1]), "r"(a[2]), "r"(a[3]), "r"(b[0]), "r"(b[1]));
}

// ---------------- split/convert kernels ----------------
__global__ __launch_bounds__(256) void convert_split_kernel(
    const float* __restrict__ in, __nv_bfloat16* __restrict__ oh,
    __nv_bfloat16* __restrict__ ol, int n)
{
    int i = blockIdx.x * blockDim.x + threadIdx.x;
    if (i < n) {
        float x = in[i];
        __nv_bfloat16 h = __float2bfloat16(x);
        oh[i] = h;
        ol[i] = __float2bfloat16(x - __bfloat162float(h));
    }
}

// in: fp32 [R, C] row-major -> out hi/lo bf16 [C, R]
__global__ __launch_bounds__(256) void transpose_split_kernel(
    const float* __restrict__ in, __nv_bfloat16* __restrict__ oh,
    __nv_bfloat16* __restrict__ ol, int R, int C)
{
    __shared__ float t[32][33];
    int bx = blockIdx.x * 32;   // C
    int by = blockIdx.y * 32;   // R
    int tx = threadIdx.x, ty = threadIdx.y;   // 32 x 8
#pragma unroll
    for (int j = 0; j < 32; j += 8)
        t[ty + j][tx] = in[(size_t)(by + ty + j) * C + bx + tx];
    __syncthreads();
#pragma unroll
    for (int j = 0; j < 32; j += 8) {
        float x = t[tx][ty + j];
        __nv_bfloat16 h = __float2bfloat16(x);
        size_t o = (size_t)(bx + ty + j) * R + by + tx;
        oh[o] = h;
        ol[o] = __float2bfloat16(x - __bfloat162float(h));
    }
}

// ---------------- mma.sync bf16-split GEMM ----------------
// C[M,N] = Ah@Bh^T + Ah@Bl^T + Al@Bh^T
// A:[M,K] K-major bf16 hi/lo; B:[N,K] K-major bf16 hi/lo (pre-transposed).
// CTA 256x128, BK=64, 16 warps (4x4), warp tile 64x32, 2-stage cp.async.
#define GEMM_BM 256
#define GEMM_BN 128
#define GEMM_BK 64
#define GEMM_THREADS 512
#define TILE_A_BYTES (GEMM_BM * GEMM_BK * 2)   // 32 KB (one of hi/lo)
#define TILE_B_BYTES (GEMM_BN * GEMM_BK * 2)   // 16 KB
#define STAGE_BYTES (2 * TILE_A_BYTES + 2 * TILE_B_BYTES)  // 96 KB
#define GEMM_SMEM (2 * STAGE_BYTES)            // 192 KB

// swizzled smem addr within a ROWSx64(bf16) tile: row pitch 128B, 16B chunks xor'd
__device__ __forceinline__ uint32_t sw_addr(uint32_t base, int row, int chunk) {
    return base + row * 128 + ((chunk ^ (row & 7)) << 4);
}

// load ROWS x 64 bf16 subtile via cp.async; ITER = ROWS*8/512 chunks per thread
template<int ITER>
__device__ __forceinline__ void load_tileN(uint32_t sbase, const __nv_bfloat16* g,
                                           int ld, int tid)
{
#pragma unroll
    for (int i = 0; i < ITER; i++) {
        int e = tid + i * GEMM_THREADS;
        int r = e >> 3;
        int c = e & 7;
        cp16(sw_addr(sbase, r, c), (const void*)(g + (size_t)r * ld + c * 8));
    }
}

__device__ __forceinline__ void load_stage(uint32_t st,
    const __nv_bfloat16* gAh, const __nv_bfloat16* gAl,
    const __nv_bfloat16* gBh, const __nv_bfloat16* gBl,
    int kk, int K, int tid)
{
    load_tileN<4>(st,                                    gAh + kk, K, tid);
    load_tileN<4>(st + TILE_A_BYTES,                     gAl + kk, K, tid);
    load_tileN<2>(st + 2 * TILE_A_BYTES,                 gBh + kk, K, tid);
    load_tileN<2>(st + 2 * TILE_A_BYTES + TILE_B_BYTES,  gBl + kk, K, tid);
    asm volatile("cp.async.commit_group;" ::: "memory");
}

__global__ __launch_bounds__(GEMM_THREADS, 1) void gemm_bf16split_kernel(
    const __nv_bfloat16* __restrict__ Ah, const __nv_bfloat16* __restrict__ Al,
    const __nv_bfloat16* __restrict__ Bh, const __nv_bfloat16* __restrict__ Bl,
    float* __restrict__ C, int M, int N, int K)
{
    extern __shared__ char smem[];
    uint32_t sb = smem_u32(smem);
    int tid = threadIdx.x;
    int warp = tid >> 5, lane = tid & 31;
    int row0 = blockIdx.y * GEMM_BM;
    int col0 = blockIdx.x * GEMM_BN;
    int wm0 = (warp >> 2) * 64;        // warp M offset (0..192)
    int wn0 = (warp & 3) * 32;         // warp N offset (0..96)

    const __nv_bfloat16* gAh = Ah + (size_t)row0 * K;
    const __nv_bfloat16* gAl = Al + (size_t)row0 * K;
    const __nv_bfloat16* gBh = Bh + (size_t)col0 * K;
    const __nv_bfloat16* gBl = Bl + (size_t)col0 * K;

    const int T = K / GEMM_BK;

    float acc[4][4][4];   // [m16][n8][frag]
#pragma unroll
    for (int m = 0; m < 4; m++)
#pragma unroll
        for (int n = 0; n < 4; n++)
#pragma unroll
            for (int f = 0; f < 4; f++) acc[m][n][f] = 0.f;

    // prologue: fill both stages
    load_stage(sb,               gAh, gAl, gBh, gBl, 0,        K, tid);
    load_stage(sb + STAGE_BYTES, gAh, gAl, gBh, gBl, GEMM_BK,  K, tid);

    // fragment address precompute (per lane)
    int mat = lane >> 3;
    int frow = (lane & 7) + ((mat & 1) << 3);   // row within 16-row group
    int fch  = mat >> 1;                        // chunk within k16 (0 or 1)

    for (int t = 0; t < T; t++) {
        if (t == T - 1) asm volatile("cp.async.wait_group 0;" ::: "memory");
        else            asm volatile("cp.async.wait_group 1;" ::: "memory");
        __syncthreads();

        uint32_t st = sb + (t & 1) * STAGE_BYTES;
        uint32_t sAh = st, sAl = st + TILE_A_BYTES;
        uint32_t sBh = st + 2 * TILE_A_BYTES, sBl = sBh + TILE_B_BYTES;

#pragma unroll
        for (int ks = 0; ks < 4; ks++) {
            int kc = ks * 2 + fch;
            uint32_t bh[2][4], bl[2][4];
#pragma unroll
            for (int g = 0; g < 2; g++) {
                int brow = wn0 + g * 16 + frow;
                ldsm_x4(bh[g], sw_addr(sBh, brow, kc));
                ldsm_x4(bl[g], sw_addr(sBl, brow, kc));
            }
#pragma unroll
            for (int m = 0; m < 4; m++) {
                int arow = wm0 + m * 16 + frow;
                uint32_t ah[4], al[4];
                ldsm_x4(ah, sw_addr(sAh, arow, kc));
                ldsm_x4(al, sw_addr(sAl, arow, kc));
#pragma unroll
                for (int n = 0; n < 4; n++) {
                    int g = n >> 1, h = n & 1;
                    uint32_t bhf[2] = {bh[g][h], bh[g][h + 2]};
                    uint32_t blf[2] = {bl[g][h], bl[g][h + 2]};
                    mma16816(acc[m][n], ah, bhf);   // hi*hi
                    mma16816(acc[m][n], ah, blf);   // hi*lo
                    mma16816(acc[m][n], al, bhf);   // lo*hi
                }
            }
        }
        __syncthreads();

        if (t + 2 < T)
            load_stage(st, gAh, gAl, gBh, gBl, (t + 2) * GEMM_BK, K, tid);
    }

    // epilogue: write fp32 C
#pragma unroll
    for (int m = 0; m < 4; m++) {
        int r0 = row0 + wm0 + m * 16 + (lane >> 2);
#pragma unroll
        for (int n = 0; n < 4; n++) {
            int c = col0 + wn0 + n * 8 + (lane & 3) * 2;
            *(float2*)&C[(size_t)r0 * N + c]       = make_float2(acc[m][n][0], acc[m][n][1]);
            *(float2*)&C[(size_t)(r0 + 8) * N + c] = make_float2(acc[m][n][2], acc[m][n][3]);
        }
    }
}

// ---------------- fused per-head RMSNorm + RoPE (in place) ----------------
__global__ __launch_bounds__(128) void rmsnorm_rope_kernel(
    float* __restrict__ X, const float* __restrict__ w, int n_heads)
{
    int row = blockIdx.x;
    int t = (row / n_heads) % TT;
    int d = threadIdx.x;
    float* xr = X + (size_t)row * HD;

    float v = xr[d];
    float s = v * v;
#pragma unroll
    for (int off = 16; off; off >>= 1) s += __shfl_xor_sync(0xffffffffu, s, off);

    __shared__ float red[4];
    __shared__ float xs[HD];
    int warp = d >> 5, lane = d & 31;
    if (lane == 0) red[warp] = s;
    __syncthreads();
    float tot = red[0] + red[1] + red[2] + red[3];
    float rinv = rsqrtf(tot * (1.0f / HD) + 1e-6f);
    float xn = w[d] * v * rinv;
    xs[d] = xn;
    __syncthreads();

    if (d < 64) {
        float a = xs[d];
        float b = xs[d + 64];
        double freq = pow(1.0e6, -(double)(2 * d) / 128.0);
        double ang = (double)t * freq;
        double sn, cs;
        sincos(ang, &sn, &cs);
        float fs = (float)sn, fc = (float)cs;
        xr[d]      = a * fc - b * fs;
        xr[d + 64] = b * fc + a * fs;
    }
}

// ---------------- fp32 causal GQA flash attention ----------------
#define FBM 64
#define FBN 64
#define PP  68
#define FTHREADS 256

__global__ __launch_bounds__(FTHREADS) void flash_kernel(
    const float* __restrict__ Q, const float* __restrict__ Kb,
    const float* __restrict__ Vb, float* __restrict__ O)
{
    extern __shared__ float smf[];
    float* Qs  = smf;
    float* Ks  = Qs + HD * FBM;
    float* Vs  = Ks + HD * FBN;
    float* Ps  = Vs + FBN * HD;
    float* m_s = Ps + FBM * PP;
    float* l_s = m_s + FBM;
    float* a_s = l_s + FBM;

    int tid = threadIdx.x;
    int tx = tid & 15, ty = tid >> 4;
    int lane = tid & 31, warp = tid >> 5;
    int qt0 = blockIdx.x * FBM;
    int h = blockIdx.y;
    int b = blockIdx.z;
    int kvh = h / GROUPS;

    const float* Qp = Q + ((size_t)(b * TT + qt0) * NH + h) * HD;
#pragma unroll
    for (int i = 0; i < 8; i++) {
        int e = tid + i * FTHREADS;
        int r = e >> 5;
        int c4 = (e & 31) << 2;
        float4 q4 = *(const float4*)&Qp[(size_t)r * NH * HD + c4];
        Qs[(c4 + 0) * FBM + r] = q4.x;
        Qs[(c4 + 1) * FBM + r] = q4.y;
        Qs[(c4 + 2) * FBM + r] = q4.z;
        Qs[(c4 + 3) * FBM + r] = q4.w;
    }
    if (tid < FBM) { m_s[tid] = -1e30f; l_s[tid] = 0.f; }

    float acc[4][8];
#pragma unroll
    for (int i = 0; i < 4; i++)
#pragma unroll
        for (int j = 0; j < 8; j++) acc[i][j] = 0.f;

    int r0 = ty * 4;
    int cS0 = tx * 4;
    int d0 = tx * 8;
    const float scale = 0.08838834764831845f;

    int n_kt = qt0 / FBN + 1;
    for (int kt = 0; kt < n_kt; kt++) {
        int kt0 = kt * FBN;
        const float* Kp = Kb + ((size_t)(b * TT + kt0) * NKV + kvh) * HD;
        const float* Vp = Vb + ((size_t)(b * TT + kt0) * NKV + kvh) * HD;

        __syncthreads();

#pragma unroll
        for (int i = 0; i < 8; i++) {
            int e = tid + i * FTHREADS;
            int r = e >> 5;
            int c4 = (e & 31) << 2;
            float4 k4 = *(const float4*)&Kp[(size_t)r * NKV * HD + c4];
            Ks[(c4 + 0) * FBN + r] = k4.x;
            Ks[(c4 + 1) * FBN + r] = k4.y;
            Ks[(c4 + 2) * FBN + r] = k4.z;
            Ks[(c4 + 3) * FBN + r] = k4.w;
            float4 v4 = *(const float4*)&Vp[(size_t)r * NKV * HD + c4];
            *(float4*)&Vs[r * HD + c4] = v4;
        }
        __syncthreads();

        float sacc[4][4];
#pragma unroll
        for (int i = 0; i < 4; i++)
#pragma unroll
            for (int j = 0; j < 4; j++) sacc[i][j] = 0.f;
#pragma unroll 4
        for (int k = 0; k < HD; k++) {
            float4 qa = *(float4*)&Qs[k * FBM + r0];
            float4 ka = *(float4*)&Ks[k * FBN + cS0];
            float qv[4] = {qa.x, qa.y, qa.z, qa.w};
            float kv[4] = {ka.x, ka.y, ka.z, ka.w};
#pragma unroll
            for (int i = 0; i < 4; i++)
#pragma unroll
                for (int j = 0; j < 4; j++)
                    sacc[i][j] += qv[i] * kv[j];
        }
#pragma unroll
        for (int i = 0; i < 4; i++) {
            float4 v = make_float4(sacc[i][0] * scale, sacc[i][1] * scale,
                                   sacc[i][2] * scale, sacc[i][3] * scale);
            *(float4*)&Ps[(r0 + i) * PP + cS0] = v;
        }
        __syncthreads();

#pragma unroll
        for (int rr = 0; rr < 8; rr++) {
            int r = warp * 8 + rr;
            int gq = qt0 + r;
            int c0 = lane, c1 = lane + 32;
            bool ok0 = (kt0 + c0) <= gq;
            bool ok1 = (kt0 + c1) <= gq;
            float s0 = ok0 ? Ps[r * PP + c0] : -1e30f;
            float s1 = ok1 ? Ps[r * PP + c1] : -1e30f;
            float mx = fmaxf(s0, s1);
#pragma unroll
            for (int off = 16; off; off >>= 1)
                mx = fmaxf(mx, __shfl_xor_sync(0xffffffffu, mx, off));
            float m_old = m_s[r];
            float m_new = fmaxf(m_old, mx);
            float p0 = ok0 ? expf(s0 - m_new) : 0.f;
            float p1 = ok1 ? expf(s1 - m_new) : 0.f;
            Ps[r * PP + c0] = p0;
            Ps[r * PP + c1] = p1;
            float sum = p0 + p1;
#pragma unroll
            for (int off = 16; off; off >>= 1)
                sum += __shfl_xor_sync(0xffffffffu, sum, off);
            if (lane == 0) {
                float alpha = expf(m_old - m_new);
                l_s[r] = l_s[r] * alpha + sum;
                m_s[r] = m_new;
                a_s[r] = alpha;
            }
        }
        __syncthreads();

        float al[4];
#pragma unroll
        for (int i = 0; i < 4; i++) {
            al[i] = a_s[r0 + i];
#pragma unroll
            for (int j = 0; j < 8; j++) acc[i][j] *= al[i];
        }
#pragma unroll 2
        for (int c = 0; c < FBN; c++) {
            float4 v0 = *(float4*)&Vs[c * HD + d0];
            float4 v1 = *(float4*)&Vs[c * HD + d0 + 4];
            float vv[8] = {v0.x, v0.y, v0.z, v0.w, v1.x, v1.y, v1.z, v1.w};
#pragma unroll
            for (int i = 0; i < 4; i++) {
                float p = Ps[(r0 + i) * PP + c];
#pragma unroll
                for (int j = 0; j < 8; j++) acc[i][j] += p * vv[j];
            }
        }
    }

#pragma unroll
    for (int i = 0; i < 4; i++) {
        int r = r0 + i;
        float inv = 1.f / l_s[r];
        float* op = O + ((size_t)(b * TT + qt0 + r) * NH + h) * HD + d0;
        float4 o0 = make_float4(acc[i][0] * inv, acc[i][1] * inv, acc[i][2] * inv, acc[i][3] * inv);
        float4 o1 = make_float4(acc[i][4] * inv, acc[i][5] * inv, acc[i][6] * inv, acc[i][7] * inv);
        *(float4*)&op[0] = o0;
        *(float4*)&op[4] = o1;
    }
}

// ---------------- launch ----------------
extern "C" void kernel_launch(void* const* d_in, const int* in_sizes, int n_in,
                              void* d_out, int out_size)
{
    const float* x   = (const float*)d_in[0];
    const float* wq  = (const float*)d_in[1];
    const float* wk  = (const float*)d_in[2];
    const float* wv  = (const float*)d_in[3];
    const float* wo  = (const float*)d_in[4];
    const float* qnw = (const float*)d_in[5];
    const float* knw = (const float*)d_in[6];
    float* out = (float*)d_out;

    __nv_bfloat16 *xh, *xl, *wqth, *wqtl, *wkth, *wktl, *wvth, *wvtl, *woth, *wotl, *ah, *al;
    float *qb, *kb, *vb, *ab;
    cudaGetSymbolAddress((void**)&xh, g_xh);      cudaGetSymbolAddress((void**)&xl, g_xl);
    cudaGetSymbolAddress((void**)&wqth, g_wqt_h); cudaGetSymbolAddress((void**)&wqtl, g_wqt_l);
    cudaGetSymbolAddress((void**)&wkth, g_wkt_h); cudaGetSymbolAddress((void**)&wktl, g_wkt_l);
    cudaGetSymbolAddress((void**)&wvth, g_wvt_h); cudaGetSymbolAddress((void**)&wvtl, g_wvt_l);
    cudaGetSymbolAddress((void**)&woth, g_wot_h); cudaGetSymbolAddress((void**)&wotl, g_wot_l);
    cudaGetSymbolAddress((void**)&ah, g_ah);      cudaGetSymbolAddress((void**)&al, g_al);
    cudaGetSymbolAddress((void**)&qb, g_q);
    cudaGetSymbolAddress((void**)&kb, g_k);
    cudaGetSymbolAddress((void**)&vb, g_v);
    cudaGetSymbolAddress((void**)&ab, g_attn);

    // split x, transpose+split weights
    convert_split_kernel<<<(MROWS * HID + 255) / 256, 256>>>(x, xh, xl, MROWS * HID);
    transpose_split_kernel<<<dim3(NQ / 32, HID / 32), dim3(32, 8)>>>(wq, wqth, wqtl, HID, NQ);
    transpose_split_kernel<<<dim3(NKVD / 32, HID / 32), dim3(32, 8)>>>(wk, wkth, wktl, HID, NKVD);
    transpose_split_kernel<<<dim3(NKVD / 32, HID / 32), dim3(32, 8)>>>(wv, wvth, wvtl, HID, NKVD);
    transpose_split_kernel<<<dim3(HID / 32, NQ / 32), dim3(32, 8)>>>(wo, woth, wotl, NQ, HID);

    cudaFuncSetAttribute(gemm_bf16split_kernel,
                         cudaFuncAttributeMaxDynamicSharedMemorySize, GEMM_SMEM);

    // QKV projections (mma.sync bf16-split)
    gemm_bf16split_kernel<<<dim3(NQ / GEMM_BN, MROWS / GEMM_BM), GEMM_THREADS, GEMM_SMEM>>>(
        xh, xl, wqth, wqtl, qb, MROWS, NQ, HID);
    gemm_bf16split_kernel<<<dim3(NKVD / GEMM_BN, MROWS / GEMM_BM), GEMM_THREADS, GEMM_SMEM>>>(
        xh, xl, wkth, wktl, kb, MROWS, NKVD, HID);
    gemm_bf16split_kernel<<<dim3(NKVD / GEMM_BN, MROWS / GEMM_BM), GEMM_THREADS, GEMM_SMEM>>>(
        xh, xl, wvth, wvtl, vb, MROWS, NKVD, HID);

    // per-head RMSNorm + RoPE (in place)
    rmsnorm_rope_kernel<<<MROWS * NH, 128>>>(qb, qnw, NH);
    rmsnorm_rope_kernel<<<MROWS * NKV, 128>>>(kb, knw, NKV);

    // flash attention (fp32)
    int smem = (HD * FBM + HD * FBN + FBN * HD + FBM * PP + 3 * FBM) * (int)sizeof(float);
    cudaFuncSetAttribute(flash_kernel, cudaFuncAttributeMaxDynamicSharedMemorySize, smem);
    flash_kernel<<<dim3(TT / FBM, NH, BB), FTHREADS, smem>>>(qb, kb, vb, ab);

    // split attn output, then output projection
    convert_split_kernel<<<(MROWS * NQ + 255) / 256, 256>>>(ab, ah, al, MROWS * NQ);
    gemm_bf16split_kernel<<<dim3(HID / GEMM_BN, MROWS / GEMM_BM), GEMM_THREADS, GEMM_SMEM>>>(
        ah, al, woth, wotl, out, MROWS, HID, NQ);
}

// round 5
// speedup vs baseline: 1.1316x; 1.1316x over previous
#include <cuda_runtime.h>
#include <cuda_fp16.h>
#include <math.h>
#include <stdint.h>

// ---------------- problem constants ----------------
#define BB    2
#define TT    2048
#define HID   4096
#define NH    32
#define NKV   8
#define HD    128
#define MROWS (BB*TT)      // 4096
#define NQ    (NH*HD)      // 4096
#define NKVD  (NKV*HD)     // 1024
#define GROUPS (NH/NKV)    // 4

// ---------------- scratch (device globals, no allocation) ----------------
__device__ __half g_xh[(size_t)MROWS * HID];
__device__ __half g_xl[(size_t)MROWS * HID];
__device__ __half g_wqt[(size_t)NQ * HID];
__device__ __half g_wkt[(size_t)NKVD * HID];
__device__ __half g_wvt[(size_t)NKVD * HID];
__device__ __half g_wot[(size_t)HID * NQ];
__device__ __half g_ah[(size_t)MROWS * NQ], g_al[(size_t)MROWS * NQ];
__device__ float g_q[(size_t)MROWS * NQ];
__device__ float g_k[(size_t)MROWS * NKVD];
__device__ float g_v[(size_t)MROWS * NKVD];
__device__ float g_attn[(size_t)MROWS * NQ];

// ---------------- PTX helpers (base ISA only) ----------------
__device__ __forceinline__ uint32_t smem_u32(const void* p) {
    uint32_t a;
    asm("{ .reg .u64 t; cvta.to.shared.u64 t, %1; cvt.u32.u64 %0, t; }" : "=r"(a) : "l"(p));
    return a;
}

__device__ __forceinline__ void cp16(uint32_t dst, const void* src) {
    asm volatile("cp.async.cg.shared.global [%0], [%1], 16;" :: "r"(dst), "l"(src));
}

__device__ __forceinline__ void ldsm_x4(uint32_t* r, uint32_t addr) {
    asm volatile("ldmatrix.sync.aligned.m8n8.x4.shared.b16 {%0,%1,%2,%3}, [%4];"
                 : "=r"(r[0]), "=r"(r[1]), "=r"(r[2]), "=r"(r[3]) : "r"(addr));
}

__device__ __forceinline__ void mma16816(float* d, const uint32_t* a, const uint32_t* b) {
    asm volatile(
        "mma.sync.aligned.m16n8k16.row.col.f32.f16.f16.f32 "
        "{%0,%1,%2,%3}, {%4,%5,%6,%7}, {%8,%9}, {%0,%1,%2,%3};"
        : "+f"(d[0]), "+f"(d[1]), "+f"(d[2]), "+f"(d[3])
        : "r"(a[0]), "r"(a[1]), "r"(a[2]), "r"(a[3]), "r"(b[0]), "r"(b[1]));
}

// ---------------- split/convert kernels ----------------
// fp32 -> fp16 hi + fp16 residual
__global__ __launch_bounds__(256) void convert_split_kernel(
    const float* __restrict__ in, __half* __restrict__ oh,
    __half* __restrict__ ol, int n)
{
    int i = blockIdx.x * blockDim.x + threadIdx.x;
    if (i < n) {
        float x = in[i];
        __half h = __float2half(x);
        oh[i] = h;
        ol[i] = __float2half(x - __half2float(h));
    }
}

// in: fp32 [R, C] row-major -> out fp16 single [C, R]
__global__ __launch_bounds__(256) void transpose_f16_kernel(
    const float* __restrict__ in, __half* __restrict__ o, int R, int C)
{
    __shared__ float t[32][33];
    int bx = blockIdx.x * 32;   // C
    int by = blockIdx.y * 32;   // R
    int tx = threadIdx.x, ty = threadIdx.y;   // 32 x 8
#pragma unroll
    for (int j = 0; j < 32; j += 8)
        t[ty + j][tx] = in[(size_t)(by + ty + j) * C + bx + tx];
    __syncthreads();
#pragma unroll
    for (int j = 0; j < 32; j += 8)
        o[(size_t)(bx + ty + j) * R + by + tx] = __float2half(t[tx][ty + j]);
}

// ---------------- mma.sync fp16 2-term GEMM ----------------
// C[M,N] = Ah@B^T + Al@B^T   (A split into fp16 hi/lo; B single fp16, pre-transposed [N,K])
// CTA 256x128, BK=64, 16 warps (4x4), warp tile 64x32, 2-stage cp.async.
#define GEMM_BM 256
#define GEMM_BN 128
#define GEMM_BK 64
#define GEMM_THREADS 512
#define TILE_A_BYTES (GEMM_BM * GEMM_BK * 2)   // 32 KB (one of hi/lo)
#define TILE_B_BYTES (GEMM_BN * GEMM_BK * 2)   // 16 KB
#define STAGE_BYTES (2 * TILE_A_BYTES + TILE_B_BYTES)  // 80 KB
#define GEMM_SMEM (2 * STAGE_BYTES)            // 160 KB

// swizzled smem addr within a ROWSx64(fp16) tile: row pitch 128B, 16B chunks xor'd
__device__ __forceinline__ uint32_t sw_addr(uint32_t base, int row, int chunk) {
    return base + row * 128 + ((chunk ^ (row & 7)) << 4);
}

// load ROWS x 64 fp16 subtile via cp.async; ITER = ROWS*8/512 chunks per thread
template<int ITER>
__device__ __forceinline__ void load_tileN(uint32_t sbase, const __half* g,
                                           int ld, int tid)
{
#pragma unroll
    for (int i = 0; i < ITER; i++) {
        int e = tid + i * GEMM_THREADS;
        int r = e >> 3;
        int c = e & 7;
        cp16(sw_addr(sbase, r, c), (const void*)(g + (size_t)r * ld + c * 8));
    }
}

__device__ __forceinline__ void load_stage(uint32_t st,
    const __half* gAh, const __half* gAl, const __half* gB,
    int kk, int K, int tid)
{
    load_tileN<4>(st,                    gAh + kk, K, tid);
    load_tileN<4>(st + TILE_A_BYTES,     gAl + kk, K, tid);
    load_tileN<2>(st + 2 * TILE_A_BYTES, gB + kk, K, tid);
    asm volatile("cp.async.commit_group;" ::: "memory");
}

__global__ __launch_bounds__(GEMM_THREADS, 1) void gemm_f16split_kernel(
    const __half* __restrict__ Ah, const __half* __restrict__ Al,
    const __half* __restrict__ B, float* __restrict__ C, int M, int N, int K)
{
    extern __shared__ char smem[];
    uint32_t sb = smem_u32(smem);
    int tid = threadIdx.x;
    int warp = tid >> 5, lane = tid & 31;
    int row0 = blockIdx.y * GEMM_BM;
    int col0 = blockIdx.x * GEMM_BN;
    int wm0 = (warp >> 2) * 64;        // warp M offset (0..192)
    int wn0 = (warp & 3) * 32;         // warp N offset (0..96)

    const __half* gAh = Ah + (size_t)row0 * K;
    const __half* gAl = Al + (size_t)row0 * K;
    const __half* gB  = B  + (size_t)col0 * K;

    const int T = K / GEMM_BK;

    float acc[4][4][4];   // [m16][n8][frag]
#pragma unroll
    for (int m = 0; m < 4; m++)
#pragma unroll
        for (int n = 0; n < 4; n++)
#pragma unroll
            for (int f = 0; f < 4; f++) acc[m][n][f] = 0.f;

    // prologue: fill both stages
    load_stage(sb,               gAh, gAl, gB, 0,       K, tid);
    load_stage(sb + STAGE_BYTES, gAh, gAl, gB, GEMM_BK, K, tid);

    // fragment address precompute (per lane)
    int mat = lane >> 3;
    int frow = (lane & 7) + ((mat & 1) << 3);   // row within 16-row group
    int fch  = mat >> 1;                        // chunk within k16 (0 or 1)

    for (int t = 0; t < T; t++) {
        if (t == T - 1) asm volatile("cp.async.wait_group 0;" ::: "memory");
        else            asm volatile("cp.async.wait_group 1;" ::: "memory");
        __syncthreads();

        uint32_t st = sb + (t & 1) * STAGE_BYTES;
        uint32_t sAh = st, sAl = st + TILE_A_BYTES;
        uint32_t sB  = st + 2 * TILE_A_BYTES;

#pragma unroll
        for (int ks = 0; ks < 4; ks++) {
            int kc = ks * 2 + fch;
            uint32_t bf[2][4];
#pragma unroll
            for (int g = 0; g < 2; g++) {
                int brow = wn0 + g * 16 + frow;
                ldsm_x4(bf[g], sw_addr(sB, brow, kc));
            }
#pragma unroll
            for (int m = 0; m < 4; m++) {
                int arow = wm0 + m * 16 + frow;
                uint32_t ah[4], al[4];
                ldsm_x4(ah, sw_addr(sAh, arow, kc));
                ldsm_x4(al, sw_addr(sAl, arow, kc));
#pragma unroll
                for (int n = 0; n < 4; n++) {
                    int g = n >> 1, h = n & 1;
                    uint32_t bff[2] = {bf[g][h], bf[g][h + 2]};
                    mma16816(acc[m][n], ah, bff);   // hi * B
                    mma16816(acc[m][n], al, bff);   // lo * B
                }
            }
        }
        __syncthreads();

        if (t + 2 < T)
            load_stage(st, gAh, gAl, gB, (t + 2) * GEMM_BK, K, tid);
    }

    // epilogue: write fp32 C
#pragma unroll
    for (int m = 0; m < 4; m++) {
        int r0 = row0 + wm0 + m * 16 + (lane >> 2);
#pragma unroll
        for (int n = 0; n < 4; n++) {
            int c = col0 + wn0 + n * 8 + (lane & 3) * 2;
            *(float2*)&C[(size_t)r0 * N + c]       = make_float2(acc[m][n][0], acc[m][n][1]);
            *(float2*)&C[(size_t)(r0 + 8) * N + c] = make_float2(acc[m][n][2], acc[m][n][3]);
        }
    }
}

// ---------------- fused per-head RMSNorm + RoPE (in place) ----------------
__global__ __launch_bounds__(128) void rmsnorm_rope_kernel(
    float* __restrict__ X, const float* __restrict__ w, int n_heads)
{
    int row = blockIdx.x;
    int t = (row / n_heads) % TT;
    int d = threadIdx.x;
    float* xr = X + (size_t)row * HD;

    float v = xr[d];
    float s = v * v;
#pragma unroll
    for (int off = 16; off; off >>= 1) s += __shfl_xor_sync(0xffffffffu, s, off);

    __shared__ float red[4];
    __shared__ float xs[HD];
    int warp = d >> 5, lane = d & 31;
    if (lane == 0) red[warp] = s;
    __syncthreads();
    float tot = red[0] + red[1] + red[2] + red[3];
    float rinv = rsqrtf(tot * (1.0f / HD) + 1e-6f);
    float xn = w[d] * v * rinv;
    xs[d] = xn;
    __syncthreads();

    if (d < 64) {
        float a = xs[d];
        float b = xs[d + 64];
        double freq = pow(1.0e6, -(double)(2 * d) / 128.0);
        double ang = (double)t * freq;
        double sn, cs;
        sincos(ang, &sn, &cs);
        float fs = (float)sn, fc = (float)cs;
        xr[d]      = a * fc - b * fs;
        xr[d + 64] = b * fc + a * fs;
    }
}

// ---------------- fp32 causal GQA flash attention ----------------
#define FBM 64
#define FBN 64
#define PP  68
#define FTHREADS 256

__global__ __launch_bounds__(FTHREADS) void flash_kernel(
    const float* __restrict__ Q, const float* __restrict__ Kb,
    const float* __restrict__ Vb, float* __restrict__ O)
{
    extern __shared__ float smf[];
    float* Qs  = smf;
    float* Ks  = Qs + HD * FBM;
    float* Vs  = Ks + HD * FBN;
    float* Ps  = Vs + FBN * HD;
    float* m_s = Ps + FBM * PP;
    float* l_s = m_s + FBM;
    float* a_s = l_s + FBM;

    int tid = threadIdx.x;
    int tx = tid & 15, ty = tid >> 4;
    int lane = tid & 31, warp = tid >> 5;
    int qt0 = blockIdx.x * FBM;
    int h = blockIdx.y;
    int b = blockIdx.z;
    int kvh = h / GROUPS;

    const float* Qp = Q + ((size_t)(b * TT + qt0) * NH + h) * HD;
#pragma unroll
    for (int i = 0; i < 8; i++) {
        int e = tid + i * FTHREADS;
        int r = e >> 5;
        int c4 = (e & 31) << 2;
        float4 q4 = *(const float4*)&Qp[(size_t)r * NH * HD + c4];
        Qs[(c4 + 0) * FBM + r] = q4.x;
        Qs[(c4 + 1) * FBM + r] = q4.y;
        Qs[(c4 + 2) * FBM + r] = q4.z;
        Qs[(c4 + 3) * FBM + r] = q4.w;
    }
    if (tid < FBM) { m_s[tid] = -1e30f; l_s[tid] = 0.f; }

    float acc[4][8];
#pragma unroll
    for (int i = 0; i < 4; i++)
#pragma unroll
        for (int j = 0; j < 8; j++) acc[i][j] = 0.f;

    int r0 = ty * 4;
    int cS0 = tx * 4;
    int d0 = tx * 8;
    const float scale = 0.08838834764831845f;

    int n_kt = qt0 / FBN + 1;
    for (int kt = 0; kt < n_kt; kt++) {
        int kt0 = kt * FBN;
        const float* Kp = Kb + ((size_t)(b * TT + kt0) * NKV + kvh) * HD;
        const float* Vp = Vb + ((size_t)(b * TT + kt0) * NKV + kvh) * HD;

        __syncthreads();

#pragma unroll
        for (int i = 0; i < 8; i++) {
            int e = tid + i * FTHREADS;
            int r = e >> 5;
            int c4 = (e & 31) << 2;
            float4 k4 = *(const float4*)&Kp[(size_t)r * NKV * HD + c4];
            Ks[(c4 + 0) * FBN + r] = k4.x;
            Ks[(c4 + 1) * FBN + r] = k4.y;
            Ks[(c4 + 2) * FBN + r] = k4.z;
            Ks[(c4 + 3) * FBN + r] = k4.w;
            float4 v4 = *(const float4*)&Vp[(size_t)r * NKV * HD + c4];
            *(float4*)&Vs[r * HD + c4] = v4;
        }
        __syncthreads();

        float sacc[4][4];
#pragma unroll
        for (int i = 0; i < 4; i++)
#pragma unroll
            for (int j = 0; j < 4; j++) sacc[i][j] = 0.f;
#pragma unroll 4
        for (int k = 0; k < HD; k++) {
            float4 qa = *(float4*)&Qs[k * FBM + r0];
            float4 ka = *(float4*)&Ks[k * FBN + cS0];
            float qv[4] = {qa.x, qa.y, qa.z, qa.w};
            float kv[4] = {ka.x, ka.y, ka.z, ka.w};
#pragma unroll
            for (int i = 0; i < 4; i++)
#pragma unroll
                for (int j = 0; j < 4; j++)
                    sacc[i][j] += qv[i] * kv[j];
        }
#pragma unroll
        for (int i = 0; i < 4; i++) {
            float4 v = make_float4(sacc[i][0] * scale, sacc[i][1] * scale,
                                   sacc[i][2] * scale, sacc[i][3] * scale);
            *(float4*)&Ps[(r0 + i) * PP + cS0] = v;
        }
        __syncthreads();

#pragma unroll
        for (int rr = 0; rr < 8; rr++) {
            int r = warp * 8 + rr;
            int gq = qt0 + r;
            int c0 = lane, c1 = lane + 32;
            bool ok0 = (kt0 + c0) <= gq;
            bool ok1 = (kt0 + c1) <= gq;
            float s0 = ok0 ? Ps[r * PP + c0] : -1e30f;
            float s1 = ok1 ? Ps[r * PP + c1] : -1e30f;
            float mx = fmaxf(s0, s1);
#pragma unroll
            for (int off = 16; off; off >>= 1)
                mx = fmaxf(mx, __shfl_xor_sync(0xffffffffu, mx, off));
            float m_old = m_s[r];
            float m_new = fmaxf(m_old, mx);
            float p0 = ok0 ? expf(s0 - m_new) : 0.f;
            float p1 = ok1 ? expf(s1 - m_new) : 0.f;
            Ps[r * PP + c0] = p0;
            Ps[r * PP + c1] = p1;
            float sum = p0 + p1;
#pragma unroll
            for (int off = 16; off; off >>= 1)
                sum += __shfl_xor_sync(0xffffffffu, sum, off);
            if (lane == 0) {
                float alpha = expf(m_old - m_new);
                l_s[r] = l_s[r] * alpha + sum;
                m_s[r] = m_new;
                a_s[r] = alpha;
            }
        }
        __syncthreads();

        float al[4];
#pragma unroll
        for (int i = 0; i < 4; i++) {
            al[i] = a_s[r0 + i];
#pragma unroll
            for (int j = 0; j < 8; j++) acc[i][j] *= al[i];
        }
#pragma unroll 2
        for (int c = 0; c < FBN; c++) {
            float4 v0 = *(float4*)&Vs[c * HD + d0];
            float4 v1 = *(float4*)&Vs[c * HD + d0 + 4];
            float vv[8] = {v0.x, v0.y, v0.z, v0.w, v1.x, v1.y, v1.z, v1.w};
#pragma unroll
            for (int i = 0; i < 4; i++) {
                float p = Ps[(r0 + i) * PP + c];
#pragma unroll
                for (int j = 0; j < 8; j++) acc[i][j] += p * vv[j];
            }
        }
    }

#pragma unroll
    for (int i = 0; i < 4; i++) {
        int r = r0 + i;
        float inv = 1.f / l_s[r];
        float* op = O + ((size_t)(b * TT + qt0 + r) * NH + h) * HD + d0;
        float4 o0 = make_float4(acc[i][0] * inv, acc[i][1] * inv, acc[i][2] * inv, acc[i][3] * inv);
        float4 o1 = make_float4(acc[i][4] * inv, acc[i][5] * inv, acc[i][6] * inv, acc[i][7] * inv);
        *(float4*)&op[0] = o0;
        *(float4*)&op[4] = o1;
    }
}

// ---------------- launch ----------------
extern "C" void kernel_launch(void* const* d_in, const int* in_sizes, int n_in,
                              void* d_out, int out_size)
{
    const float* x   = (const float*)d_in[0];
    const float* wq  = (const float*)d_in[1];
    const float* wk  = (const float*)d_in[2];
    const float* wv  = (const float*)d_in[3];
    const float* wo  = (const float*)d_in[4];
    const float* qnw = (const float*)d_in[5];
    const float* knw = (const float*)d_in[6];
    float* out = (float*)d_out;

    __half *xh, *xl, *wqt, *wkt, *wvt, *wot, *ah, *al;
    float *qb, *kb, *vb, *ab;
    cudaGetSymbolAddress((void**)&xh, g_xh);   cudaGetSymbolAddress((void**)&xl, g_xl);
    cudaGetSymbolAddress((void**)&wqt, g_wqt); cudaGetSymbolAddress((void**)&wkt, g_wkt);
    cudaGetSymbolAddress((void**)&wvt, g_wvt); cudaGetSymbolAddress((void**)&wot, g_wot);
    cudaGetSymbolAddress((void**)&ah, g_ah);   cudaGetSymbolAddress((void**)&al, g_al);
    cudaGetSymbolAddress((void**)&qb, g_q);
    cudaGetSymbolAddress((void**)&kb, g_k);
    cudaGetSymbolAddress((void**)&vb, g_v);
    cudaGetSymbolAddress((void**)&ab, g_attn);

    // split x (fp16 hi/lo), transpose weights to fp16 [N,K]
    convert_split_kernel<<<(MROWS * HID + 255) / 256, 256>>>(x, xh, xl, MROWS * HID);
    transpose_f16_kernel<<<dim3(NQ / 32, HID / 32), dim3(32, 8)>>>(wq, wqt, HID, NQ);
    transpose_f16_kernel<<<dim3(NKVD / 32, HID / 32), dim3(32, 8)>>>(wk, wkt, HID, NKVD);
    transpose_f16_kernel<<<dim3(NKVD / 32, HID / 32), dim3(32, 8)>>>(wv, wvt, HID, NKVD);
    transpose_f16_kernel<<<dim3(HID / 32, NQ / 32), dim3(32, 8)>>>(wo, wot, NQ, HID);

    cudaFuncSetAttribute(gemm_f16split_kernel,
                         cudaFuncAttributeMaxDynamicSharedMemorySize, GEMM_SMEM);

    // QKV projections (mma.sync fp16 2-term)
    gemm_f16split_kernel<<<dim3(NQ / GEMM_BN, MROWS / GEMM_BM), GEMM_THREADS, GEMM_SMEM>>>(
        xh, xl, wqt, qb, MROWS, NQ, HID);
    gemm_f16split_kernel<<<dim3(NKVD / GEMM_BN, MROWS / GEMM_BM), GEMM_THREADS, GEMM_SMEM>>>(
        xh, xl, wkt, kb, MROWS, NKVD, HID);
    gemm_f16split_kernel<<<dim3(NKVD / GEMM_BN, MROWS / GEMM_BM), GEMM_THREADS, GEMM_SMEM>>>(
        xh, xl, wvt, vb, MROWS, NKVD, HID);

    // per-head RMSNorm + RoPE (in place)
    rmsnorm_rope_kernel<<<MROWS * NH, 128>>>(qb, qnw, NH);
    rmsnorm_rope_kernel<<<MROWS * NKV, 128>>>(kb, knw, NKV);

    // flash attention (fp32)
    int smem = (HD * FBM + HD * FBN + FBN * HD + FBM * PP + 3 * FBM) * (int)sizeof(float);
    cudaFuncSetAttribute(flash_kernel, cudaFuncAttributeMaxDynamicSharedMemorySize, smem);
    flash_kernel<<<dim3(TT / FBM, NH, BB), FTHREADS, smem>>>(qb, kb, vb, ab);

    // split attn output (fp16 hi/lo), then output projection
    convert_split_kernel<<<(MROWS * NQ + 255) / 256, 256>>>(ab, ah, al, MROWS * NQ);
    gemm_f16split_kernel<<<dim3(HID / GEMM_BN, MROWS / GEMM_BM), GEMM_THREADS, GEMM_SMEM>>>(
        ah, al, wot, out, MROWS, HID, NQ);
}

// round 6
// speedup vs baseline: 2.0273x; 1.7915x over previous
#include <cuda_runtime.h>
#include <cuda_fp16.h>
#include <math.h>
#include <stdint.h>

// ---------------- problem constants ----------------
#define BB    2
#define TT    2048
#define HID   4096
#define NH    32
#define NKV   8
#define HD    128
#define MROWS (BB*TT)      // 4096
#define NQ    (NH*HD)      // 4096
#define NKVD  (NKV*HD)     // 1024
#define GROUPS (NH/NKV)    // 4

// ---------------- scratch (device globals, no allocation) ----------------
__device__ __half g_xh[(size_t)MROWS * HID];
__device__ __half g_xl[(size_t)MROWS * HID];
__device__ __half g_wqt[(size_t)NQ * HID];
__device__ __half g_wkt[(size_t)NKVD * HID];
__device__ __half g_wvt[(size_t)NKVD * HID];
__device__ __half g_wot[(size_t)HID * NQ];
__device__ __half g_ah[(size_t)MROWS * NQ], g_al[(size_t)MROWS * NQ];
__device__ float g_q[(size_t)MROWS * NQ];
__device__ float g_k[(size_t)MROWS * NKVD];
__device__ float g_v[(size_t)MROWS * NKVD];
__device__ float g_attn[(size_t)MROWS * NQ];

// ---------------- PTX helpers (base ISA only) ----------------
__device__ __forceinline__ uint32_t smem_u32(const void* p) {
    uint32_t a;
    asm("{ .reg .u64 t; cvta.to.shared.u64 t, %1; cvt.u32.u64 %0, t; }" : "=r"(a) : "l"(p));
    return a;
}

__device__ __forceinline__ void cp16(uint32_t dst, const void* src) {
    asm volatile("cp.async.cg.shared.global [%0], [%1], 16;" :: "r"(dst), "l"(src));
}

__device__ __forceinline__ void ldsm_x4(uint32_t* r, uint32_t addr) {
    asm volatile("ldmatrix.sync.aligned.m8n8.x4.shared.b16 {%0,%1,%2,%3}, [%4];"
                 : "=r"(r[0]), "=r"(r[1]), "=r"(r[2]), "=r"(r[3]) : "r"(addr));
}

__device__ __forceinline__ void ldsm_x4_t(uint32_t* r, uint32_t addr) {
    asm volatile("ldmatrix.sync.aligned.m8n8.x4.trans.shared.b16 {%0,%1,%2,%3}, [%4];"
                 : "=r"(r[0]), "=r"(r[1]), "=r"(r[2]), "=r"(r[3]) : "r"(addr));
}

__device__ __forceinline__ void mma16816(float* d, const uint32_t* a, const uint32_t* b) {
    asm volatile(
        "mma.sync.aligned.m16n8k16.row.col.f32.f16.f16.f32 "
        "{%0,%1,%2,%3}, {%4,%5,%6,%7}, {%8,%9}, {%0,%1,%2,%3};"
        : "+f"(d[0]), "+f"(d[1]), "+f"(d[2]), "+f"(d[3])
        : "r"(a[0]), "r"(a[1]), "r"(a[2]), "r"(a[3]), "r"(b[0]), "r"(b[1]));
}

// ---------------- split/convert kernels ----------------
__global__ __launch_bounds__(256) void convert_split_kernel(
    const float* __restrict__ in, __half* __restrict__ oh,
    __half* __restrict__ ol, int n)
{
    int i = blockIdx.x * blockDim.x + threadIdx.x;
    if (i < n) {
        float x = in[i];
        __half h = __float2half(x);
        oh[i] = h;
        ol[i] = __float2half(x - __half2float(h));
    }
}

__global__ __launch_bounds__(256) void transpose_f16_kernel(
    const float* __restrict__ in, __half* __restrict__ o, int R, int C)
{
    __shared__ float t[32][33];
    int bx = blockIdx.x * 32;   // C
    int by = blockIdx.y * 32;   // R
    int tx = threadIdx.x, ty = threadIdx.y;   // 32 x 8
#pragma unroll
    for (int j = 0; j < 32; j += 8)
        t[ty + j][tx] = in[(size_t)(by + ty + j) * C + bx + tx];
    __syncthreads();
#pragma unroll
    for (int j = 0; j < 32; j += 8)
        o[(size_t)(bx + ty + j) * R + by + tx] = __float2half(t[tx][ty + j]);
}

// ---------------- mma.sync fp16 2-term GEMM (unchanged from R5) ----------------
#define GEMM_BM 256
#define GEMM_BN 128
#define GEMM_BK 64
#define GEMM_THREADS 512
#define TILE_A_BYTES (GEMM_BM * GEMM_BK * 2)
#define TILE_B_BYTES (GEMM_BN * GEMM_BK * 2)
#define STAGE_BYTES (2 * TILE_A_BYTES + TILE_B_BYTES)
#define GEMM_SMEM (2 * STAGE_BYTES)

__device__ __forceinline__ uint32_t sw_addr(uint32_t base, int row, int chunk) {
    return base + row * 128 + ((chunk ^ (row & 7)) << 4);
}

template<int ITER>
__device__ __forceinline__ void load_tileN(uint32_t sbase, const __half* g,
                                           int ld, int tid)
{
#pragma unroll
    for (int i = 0; i < ITER; i++) {
        int e = tid + i * GEMM_THREADS;
        int r = e >> 3;
        int c = e & 7;
        cp16(sw_addr(sbase, r, c), (const void*)(g + (size_t)r * ld + c * 8));
    }
}

__device__ __forceinline__ void load_stage(uint32_t st,
    const __half* gAh, const __half* gAl, const __half* gB,
    int kk, int K, int tid)
{
    load_tileN<4>(st,                    gAh + kk, K, tid);
    load_tileN<4>(st + TILE_A_BYTES,     gAl + kk, K, tid);
    load_tileN<2>(st + 2 * TILE_A_BYTES, gB + kk, K, tid);
    asm volatile("cp.async.commit_group;" ::: "memory");
}

__global__ __launch_bounds__(GEMM_THREADS, 1) void gemm_f16split_kernel(
    const __half* __restrict__ Ah, const __half* __restrict__ Al,
    const __half* __restrict__ B, float* __restrict__ C, int M, int N, int K)
{
    extern __shared__ char smem[];
    uint32_t sb = smem_u32(smem);
    int tid = threadIdx.x;
    int warp = tid >> 5, lane = tid & 31;
    int row0 = blockIdx.y * GEMM_BM;
    int col0 = blockIdx.x * GEMM_BN;
    int wm0 = (warp >> 2) * 64;
    int wn0 = (warp & 3) * 32;

    const __half* gAh = Ah + (size_t)row0 * K;
    const __half* gAl = Al + (size_t)row0 * K;
    const __half* gB  = B  + (size_t)col0 * K;

    const int T = K / GEMM_BK;

    float acc[4][4][4];
#pragma unroll
    for (int m = 0; m < 4; m++)
#pragma unroll
        for (int n = 0; n < 4; n++)
#pragma unroll
            for (int f = 0; f < 4; f++) acc[m][n][f] = 0.f;

    load_stage(sb,               gAh, gAl, gB, 0,       K, tid);
    load_stage(sb + STAGE_BYTES, gAh, gAl, gB, GEMM_BK, K, tid);

    int mat = lane >> 3;
    int frow = (lane & 7) + ((mat & 1) << 3);
    int fch  = mat >> 1;

    for (int t = 0; t < T; t++) {
        if (t == T - 1) asm volatile("cp.async.wait_group 0;" ::: "memory");
        else            asm volatile("cp.async.wait_group 1;" ::: "memory");
        __syncthreads();

        uint32_t st = sb + (t & 1) * STAGE_BYTES;
        uint32_t sAh = st, sAl = st + TILE_A_BYTES;
        uint32_t sB  = st + 2 * TILE_A_BYTES;

#pragma unroll
        for (int ks = 0; ks < 4; ks++) {
            int kc = ks * 2 + fch;
            uint32_t bf[2][4];
#pragma unroll
            for (int g = 0; g < 2; g++) {
                int brow = wn0 + g * 16 + frow;
                ldsm_x4(bf[g], sw_addr(sB, brow, kc));
            }
#pragma unroll
            for (int m = 0; m < 4; m++) {
                int arow = wm0 + m * 16 + frow;
                uint32_t ah[4], al[4];
                ldsm_x4(ah, sw_addr(sAh, arow, kc));
                ldsm_x4(al, sw_addr(sAl, arow, kc));
#pragma unroll
                for (int n = 0; n < 4; n++) {
                    int g = n >> 1, h = n & 1;
                    uint32_t bff[2] = {bf[g][h], bf[g][h + 2]};
                    mma16816(acc[m][n], ah, bff);
                    mma16816(acc[m][n], al, bff);
                }
            }
        }
        __syncthreads();

        if (t + 2 < T)
            load_stage(st, gAh, gAl, gB, (t + 2) * GEMM_BK, K, tid);
    }

#pragma unroll
    for (int m = 0; m < 4; m++) {
        int r0 = row0 + wm0 + m * 16 + (lane >> 2);
#pragma unroll
        for (int n = 0; n < 4; n++) {
            int c = col0 + wn0 + n * 8 + (lane & 3) * 2;
            *(float2*)&C[(size_t)r0 * N + c]       = make_float2(acc[m][n][0], acc[m][n][1]);
            *(float2*)&C[(size_t)(r0 + 8) * N + c] = make_float2(acc[m][n][2], acc[m][n][3]);
        }
    }
}

// ---------------- fused per-head RMSNorm + RoPE (in place) ----------------
__global__ __launch_bounds__(128) void rmsnorm_rope_kernel(
    float* __restrict__ X, const float* __restrict__ w, int n_heads)
{
    int row = blockIdx.x;
    int t = (row / n_heads) % TT;
    int d = threadIdx.x;
    float* xr = X + (size_t)row * HD;

    float v = xr[d];
    float s = v * v;
#pragma unroll
    for (int off = 16; off; off >>= 1) s += __shfl_xor_sync(0xffffffffu, s, off);

    __shared__ float red[4];
    __shared__ float xs[HD];
    int warp = d >> 5, lane = d & 31;
    if (lane == 0) red[warp] = s;
    __syncthreads();
    float tot = red[0] + red[1] + red[2] + red[3];
    float rinv = rsqrtf(tot * (1.0f / HD) + 1e-6f);
    float xn = w[d] * v * rinv;
    xs[d] = xn;
    __syncthreads();

    if (d < 64) {
        float a = xs[d];
        float b = xs[d + 64];
        double freq = pow(1.0e6, -(double)(2 * d) / 128.0);
        double ang = (double)t * freq;
        double sn, cs;
        sincos(ang, &sn, &cs);
        float fs = (float)sn, fc = (float)cs;
        xr[d]      = a * fc - b * fs;
        xr[d + 64] = b * fc + a * fs;
    }
}

// ---------------- fp16 tensor-core causal GQA flash attention ----------------
// CTA: 128 threads (4 warps). Tile 64(q) x 64(k), D=128.
// Warp w owns query rows 16w..16w+15 (full rows -> softmax stays in registers).
// Qs/Ks/Vs: fp16 [64][128], row pitch 256B, 16B chunks swizzled by row&7.
#define FL_SMEM (3 * 64 * 256)

__device__ __forceinline__ uint32_t fl_addr(uint32_t base, int row, int chunk) {
    return base + row * 256 + ((chunk ^ (row & 7)) << 4);
}

__global__ __launch_bounds__(128) void flash16_kernel(
    const float* __restrict__ Q, const float* __restrict__ Kb,
    const float* __restrict__ Vb, float* __restrict__ O)
{
    extern __shared__ char sm[];
    uint32_t sQ = smem_u32(sm);
    uint32_t sK = sQ + 64 * 256;
    uint32_t sV = sK + 64 * 256;

    int tid = threadIdx.x, warp = tid >> 5, lane = tid & 31;
    int qt0 = blockIdx.x * 64;
    int h = blockIdx.y;
    int b = blockIdx.z;
    int kvh = h / GROUPS;
    const float scale = 0.08838834764831845f;   // 1/sqrt(128), folded into Q

    // ---- load Q tile (scaled, fp32->fp16) ----
    const float* Qp = Q + ((size_t)(b * TT + qt0) * NH + h) * HD;
#pragma unroll
    for (int i = 0; i < 16; i++) {
        int e = tid + i * 128;
        int r = e >> 5, d4 = (e & 31) * 4;
        float4 q4 = *(const float4*)&Qp[(size_t)r * NH * HD + d4];
        __half2 h0 = __floats2half2_rn(q4.x * scale, q4.y * scale);
        __half2 h1 = __floats2half2_rn(q4.z * scale, q4.w * scale);
        uint32_t byte = d4 * 2;
        uint32_t addr = fl_addr(sQ, r, byte >> 4) + (byte & 15);
        asm volatile("st.shared.v2.b32 [%0], {%1,%2};"
                     :: "r"(addr), "r"(*(uint32_t*)&h0), "r"(*(uint32_t*)&h1));
    }

    float m_lo = -1e30f, m_hi = -1e30f;   // rows 16w+(lane>>2), +8
    float l_lo = 0.f, l_hi = 0.f;
    float acc[16][4];
#pragma unroll
    for (int g = 0; g < 16; g++)
#pragma unroll
        for (int f = 0; f < 4; f++) acc[g][f] = 0.f;

    int m0 = warp * 16;
    int lrow = lane & 15;
    int lch  = lane >> 4;

    int n_kt = qt0 / 64 + 1;
    for (int kt = 0; kt < n_kt; kt++) {
        int kt0 = kt * 64;
        __syncthreads();   // previous tile's MMAs done reading sK/sV

        // ---- load K, V tiles (fp32->fp16) ----
        const float* Kp = Kb + ((size_t)(b * TT + kt0) * NKV + kvh) * HD;
        const float* Vp = Vb + ((size_t)(b * TT + kt0) * NKV + kvh) * HD;
#pragma unroll
        for (int i = 0; i < 16; i++) {
            int e = tid + i * 128;
            int r = e >> 5, d4 = (e & 31) * 4;
            uint32_t byte = d4 * 2;
            float4 k4 = *(const float4*)&Kp[(size_t)r * NKV * HD + d4];
            __half2 k0 = __floats2half2_rn(k4.x, k4.y);
            __half2 k1 = __floats2half2_rn(k4.z, k4.w);
            uint32_t ka = fl_addr(sK, r, byte >> 4) + (byte & 15);
            asm volatile("st.shared.v2.b32 [%0], {%1,%2};"
                         :: "r"(ka), "r"(*(uint32_t*)&k0), "r"(*(uint32_t*)&k1));
            float4 v4 = *(const float4*)&Vp[(size_t)r * NKV * HD + d4];
            __half2 v0 = __floats2half2_rn(v4.x, v4.y);
            __half2 v1 = __floats2half2_rn(v4.z, v4.w);
            uint32_t va = fl_addr(sV, r, byte >> 4) + (byte & 15);
            asm volatile("st.shared.v2.b32 [%0], {%1,%2};"
                         :: "r"(va), "r"(*(uint32_t*)&v0), "r"(*(uint32_t*)&v1));
        }
        __syncthreads();

        // ---- S = Q_warp @ K^T  (warp tile 16x64) ----
        float sacc[8][4];
#pragma unroll
        for (int n = 0; n < 8; n++)
#pragma unroll
            for (int f = 0; f < 4; f++) sacc[n][f] = 0.f;

#pragma unroll
        for (int ks = 0; ks < 8; ks++) {
            uint32_t a[4];
            int ar = m0 + lrow;
            ldsm_x4(a, fl_addr(sQ, ar, 2 * ks + lch));
#pragma unroll
            for (int g = 0; g < 4; g++) {
                uint32_t kf[4];
                int br = g * 16 + lrow;
                ldsm_x4(kf, fl_addr(sK, br, 2 * ks + lch));
                uint32_t b0[2] = {kf[0], kf[2]};
                uint32_t b1[2] = {kf[1], kf[3]};
                mma16816(sacc[2 * g],     a, b0);
                mma16816(sacc[2 * g + 1], a, b1);
            }
        }

        // ---- causal mask (diagonal tile only: qt0 == kt0) ----
        if (kt == n_kt - 1) {
            int r_lo = m0 + (lane >> 2);
            int r_hi = r_lo + 8;
            int cbase = (lane & 3) * 2;
#pragma unroll
            for (int n = 0; n < 8; n++) {
                int c0 = n * 8 + cbase, c1 = c0 + 1;
                if (c0 > r_lo) sacc[n][0] = -1e30f;
                if (c1 > r_lo) sacc[n][1] = -1e30f;
                if (c0 > r_hi) sacc[n][2] = -1e30f;
                if (c1 > r_hi) sacc[n][3] = -1e30f;
            }
        }

        // ---- online softmax (rows fully within warp; quad = same row) ----
        float mx_lo = -1e30f, mx_hi = -1e30f;
#pragma unroll
        for (int n = 0; n < 8; n++) {
            mx_lo = fmaxf(mx_lo, fmaxf(sacc[n][0], sacc[n][1]));
            mx_hi = fmaxf(mx_hi, fmaxf(sacc[n][2], sacc[n][3]));
        }
#pragma unroll
        for (int off = 1; off <= 2; off <<= 1) {
            mx_lo = fmaxf(mx_lo, __shfl_xor_sync(0xffffffffu, mx_lo, off));
            mx_hi = fmaxf(mx_hi, __shfl_xor_sync(0xffffffffu, mx_hi, off));
        }
        float mn_lo = fmaxf(m_lo, mx_lo);
        float mn_hi = fmaxf(m_hi, mx_hi);
        float sum_lo = 0.f, sum_hi = 0.f;
#pragma unroll
        for (int n = 0; n < 8; n++) {
            sacc[n][0] = expf(sacc[n][0] - mn_lo);
            sacc[n][1] = expf(sacc[n][1] - mn_lo);
            sacc[n][2] = expf(sacc[n][2] - mn_hi);
            sacc[n][3] = expf(sacc[n][3] - mn_hi);
            sum_lo += sacc[n][0] + sacc[n][1];
            sum_hi += sacc[n][2] + sacc[n][3];
        }
#pragma unroll
        for (int off = 1; off <= 2; off <<= 1) {
            sum_lo += __shfl_xor_sync(0xffffffffu, sum_lo, off);
            sum_hi += __shfl_xor_sync(0xffffffffu, sum_hi, off);
        }
        float al_lo = expf(m_lo - mn_lo);
        float al_hi = expf(m_hi - mn_hi);
        l_lo = l_lo * al_lo + sum_lo;  m_lo = mn_lo;
        l_hi = l_hi * al_hi + sum_hi;  m_hi = mn_hi;
#pragma unroll
        for (int g = 0; g < 16; g++) {
            acc[g][0] *= al_lo; acc[g][1] *= al_lo;
            acc[g][2] *= al_hi; acc[g][3] *= al_hi;
        }

        // ---- pack P fragments (register repack, FA2 style) ----
        uint32_t pf[4][4];
#pragma unroll
        for (int j = 0; j < 4; j++) {
            __half2 p0 = __floats2half2_rn(sacc[2*j][0],   sacc[2*j][1]);
            __half2 p1 = __floats2half2_rn(sacc[2*j][2],   sacc[2*j][3]);
            __half2 p2 = __floats2half2_rn(sacc[2*j+1][0], sacc[2*j+1][1]);
            __half2 p3 = __floats2half2_rn(sacc[2*j+1][2], sacc[2*j+1][3]);
            pf[j][0] = *(uint32_t*)&p0;
            pf[j][1] = *(uint32_t*)&p1;
            pf[j][2] = *(uint32_t*)&p2;
            pf[j][3] = *(uint32_t*)&p3;
        }

        // ---- O += P @ V  (V row-major, B-frags via ldmatrix.trans) ----
        int vrow_off = (lane & 7) + ((lane >> 3) & 1) * 8;
#pragma unroll
        for (int j = 0; j < 4; j++) {
            int c0 = j * 16;
#pragma unroll
            for (int g = 0; g < 8; g++) {
                uint32_t vf[4];
                ldsm_x4_t(vf, fl_addr(sV, c0 + vrow_off, 2 * g + lch));
                uint32_t b0[2] = {vf[0], vf[1]};
                uint32_t b1[2] = {vf[2], vf[3]};
                mma16816(acc[2 * g],     pf[j], b0);
                mma16816(acc[2 * g + 1], pf[j], b1);
            }
        }
    }

    // ---- epilogue: divide by l, write O fp32 [b][t][h][d] ----
    float inv_lo = 1.f / l_lo, inv_hi = 1.f / l_hi;
    int r_lo = qt0 + m0 + (lane >> 2);
    int r_hi = r_lo + 8;
    float* olo = O + ((size_t)(b * TT + r_lo) * NH + h) * HD;
    float* ohi = O + ((size_t)(b * TT + r_hi) * NH + h) * HD;
#pragma unroll
    for (int g = 0; g < 16; g++) {
        int d = g * 8 + (lane & 3) * 2;
        *(float2*)&olo[d] = make_float2(acc[g][0] * inv_lo, acc[g][1] * inv_lo);
        *(float2*)&ohi[d] = make_float2(acc[g][2] * inv_hi, acc[g][3] * inv_hi);
    }
}

// ---------------- launch ----------------
extern "C" void kernel_launch(void* const* d_in, const int* in_sizes, int n_in,
                              void* d_out, int out_size)
{
    const float* x   = (const float*)d_in[0];
    const float* wq  = (const float*)d_in[1];
    const float* wk  = (const float*)d_in[2];
    const float* wv  = (const float*)d_in[3];
    const float* wo  = (const float*)d_in[4];
    const float* qnw = (const float*)d_in[5];
    const float* knw = (const float*)d_in[6];
    float* out = (float*)d_out;

    __half *xh, *xl, *wqt, *wkt, *wvt, *wot, *ah, *al;
    float *qb, *kb, *vb, *ab;
    cudaGetSymbolAddress((void**)&xh, g_xh);   cudaGetSymbolAddress((void**)&xl, g_xl);
    cudaGetSymbolAddress((void**)&wqt, g_wqt); cudaGetSymbolAddress((void**)&wkt, g_wkt);
    cudaGetSymbolAddress((void**)&wvt, g_wvt); cudaGetSymbolAddress((void**)&wot, g_wot);
    cudaGetSymbolAddress((void**)&ah, g_ah);   cudaGetSymbolAddress((void**)&al, g_al);
    cudaGetSymbolAddress((void**)&qb, g_q);
    cudaGetSymbolAddress((void**)&kb, g_k);
    cudaGetSymbolAddress((void**)&vb, g_v);
    cudaGetSymbolAddress((void**)&ab, g_attn);

    // split x (fp16 hi/lo), transpose weights to fp16 [N,K]
    convert_split_kernel<<<(MROWS * HID + 255) / 256, 256>>>(x, xh, xl, MROWS * HID);
    transpose_f16_kernel<<<dim3(NQ / 32, HID / 32), dim3(32, 8)>>>(wq, wqt, HID, NQ);
    transpose_f16_kernel<<<dim3(NKVD / 32, HID / 32), dim3(32, 8)>>>(wk, wkt, HID, NKVD);
    transpose_f16_kernel<<<dim3(NKVD / 32, HID / 32), dim3(32, 8)>>>(wv, wvt, HID, NKVD);
    transpose_f16_kernel<<<dim3(HID / 32, NQ / 32), dim3(32, 8)>>>(wo, wot, NQ, HID);

    cudaFuncSetAttribute(gemm_f16split_kernel,
                         cudaFuncAttributeMaxDynamicSharedMemorySize, GEMM_SMEM);

    // QKV projections (mma.sync fp16 2-term)
    gemm_f16split_kernel<<<dim3(NQ / GEMM_BN, MROWS / GEMM_BM), GEMM_THREADS, GEMM_SMEM>>>(
        xh, xl, wqt, qb, MROWS, NQ, HID);
    gemm_f16split_kernel<<<dim3(NKVD / GEMM_BN, MROWS / GEMM_BM), GEMM_THREADS, GEMM_SMEM>>>(
        xh, xl, wkt, kb, MROWS, NKVD, HID);
    gemm_f16split_kernel<<<dim3(NKVD / GEMM_BN, MROWS / GEMM_BM), GEMM_THREADS, GEMM_SMEM>>>(
        xh, xl, wvt, vb, MROWS, NKVD, HID);

    // per-head RMSNorm + RoPE (in place)
    rmsnorm_rope_kernel<<<MROWS * NH, 128>>>(qb, qnw, NH);
    rmsnorm_rope_kernel<<<MROWS * NKV, 128>>>(kb, knw, NKV);

    // flash attention (fp16 tensor cores)
    cudaFuncSetAttribute(flash16_kernel, cudaFuncAttributeMaxDynamicSharedMemorySize, FL_SMEM);
    flash16_kernel<<<dim3(TT / 64, NH, BB), 128, FL_SMEM>>>(qb, kb, vb, ab);

    // split attn output (fp16 hi/lo), then output projection
    convert_split_kernel<<<(MROWS * NQ + 255) / 256, 256>>>(ab, ah, al, MROWS * NQ);
    gemm_f16split_kernel<<<dim3(HID / GEMM_BN, MROWS / GEMM_BM), GEMM_THREADS, GEMM_SMEM>>>(
        ah, al, wot, out, MROWS, HID, NQ);
}

// round 7
// speedup vs baseline: 2.1365x; 1.0539x over previous
#include <cuda_runtime.h>
#include <cuda_fp16.h>
#include <math.h>
#include <stdint.h>

// ---------------- problem constants ----------------
#define BB    2
#define TT    2048
#define HID   4096
#define NH    32
#define NKV   8
#define HD    128
#define MROWS (BB*TT)      // 4096
#define NQ    (NH*HD)      // 4096
#define NKVD  (NKV*HD)     // 1024
#define GROUPS (NH/NKV)    // 4

// ---------------- scratch (device globals, no allocation) ----------------
__device__ __half g_xh[(size_t)MROWS * HID];
__device__ __half g_xl[(size_t)MROWS * HID];
__device__ __half g_wqt[(size_t)NQ * HID];
__device__ __half g_wkt[(size_t)NKVD * HID];
__device__ __half g_wvt[(size_t)NKVD * HID];
__device__ __half g_wot[(size_t)HID * NQ];
__device__ __half g_ah[(size_t)MROWS * NQ], g_al[(size_t)MROWS * NQ];
__device__ float g_q[(size_t)MROWS * NQ];
__device__ float g_k[(size_t)MROWS * NKVD];
__device__ __half g_q16[(size_t)MROWS * NQ];
__device__ __half g_k16[(size_t)MROWS * NKVD];
__device__ __half g_v16[(size_t)MROWS * NKVD];

// ---------------- PTX helpers (base ISA only) ----------------
__device__ __forceinline__ uint32_t smem_u32(const void* p) {
    uint32_t a;
    asm("{ .reg .u64 t; cvta.to.shared.u64 t, %1; cvt.u32.u64 %0, t; }" : "=r"(a) : "l"(p));
    return a;
}

__device__ __forceinline__ void cp16(uint32_t dst, const void* src) {
    asm volatile("cp.async.cg.shared.global [%0], [%1], 16;" :: "r"(dst), "l"(src));
}

__device__ __forceinline__ void ldsm_x4(uint32_t* r, uint32_t addr) {
    asm volatile("ldmatrix.sync.aligned.m8n8.x4.shared.b16 {%0,%1,%2,%3}, [%4];"
                 : "=r"(r[0]), "=r"(r[1]), "=r"(r[2]), "=r"(r[3]) : "r"(addr));
}

__device__ __forceinline__ void ldsm_x4_t(uint32_t* r, uint32_t addr) {
    asm volatile("ldmatrix.sync.aligned.m8n8.x4.trans.shared.b16 {%0,%1,%2,%3}, [%4];"
                 : "=r"(r[0]), "=r"(r[1]), "=r"(r[2]), "=r"(r[3]) : "r"(addr));
}

__device__ __forceinline__ void mma16816(float* d, const uint32_t* a, const uint32_t* b) {
    asm volatile(
        "mma.sync.aligned.m16n8k16.row.col.f32.f16.f16.f32 "
        "{%0,%1,%2,%3}, {%4,%5,%6,%7}, {%8,%9}, {%0,%1,%2,%3};"
        : "+f"(d[0]), "+f"(d[1]), "+f"(d[2]), "+f"(d[3])
        : "r"(a[0]), "r"(a[1]), "r"(a[2]), "r"(a[3]), "r"(b[0]), "r"(b[1]));
}

// ---------------- split/convert kernels ----------------
__global__ __launch_bounds__(256) void convert_split_kernel(
    const float* __restrict__ in, __half* __restrict__ oh,
    __half* __restrict__ ol, int n)
{
    int i = blockIdx.x * blockDim.x + threadIdx.x;
    if (i < n) {
        float x = in[i];
        __half h = __float2half(x);
        oh[i] = h;
        ol[i] = __float2half(x - __half2float(h));
    }
}

__global__ __launch_bounds__(256) void transpose_f16_kernel(
    const float* __restrict__ in, __half* __restrict__ o, int R, int C)
{
    __shared__ float t[32][33];
    int bx = blockIdx.x * 32;   // C
    int by = blockIdx.y * 32;   // R
    int tx = threadIdx.x, ty = threadIdx.y;   // 32 x 8
#pragma unroll
    for (int j = 0; j < 32; j += 8)
        t[ty + j][tx] = in[(size_t)(by + ty + j) * C + bx + tx];
    __syncthreads();
#pragma unroll
    for (int j = 0; j < 32; j += 8)
        o[(size_t)(bx + ty + j) * R + by + tx] = __float2half(t[tx][ty + j]);
}

// ---------------- mma.sync fp16 2-term GEMM (fp32 out) ----------------
#define GEMM_BM 256
#define GEMM_BN 128
#define GEMM_BK 64
#define GEMM_THREADS 512
#define TILE_A_BYTES (GEMM_BM * GEMM_BK * 2)
#define TILE_B_BYTES (GEMM_BN * GEMM_BK * 2)
#define STAGE_BYTES (2 * TILE_A_BYTES + TILE_B_BYTES)
#define GEMM_SMEM (2 * STAGE_BYTES)
// single-term variant
#define STAGE1_BYTES (TILE_A_BYTES + TILE_B_BYTES)
#define GEMM1_SMEM (2 * STAGE1_BYTES)

__device__ __forceinline__ uint32_t sw_addr(uint32_t base, int row, int chunk) {
    return base + row * 128 + ((chunk ^ (row & 7)) << 4);
}

template<int ITER>
__device__ __forceinline__ void load_tileN(uint32_t sbase, const __half* g,
                                           int ld, int tid)
{
#pragma unroll
    for (int i = 0; i < ITER; i++) {
        int e = tid + i * GEMM_THREADS;
        int r = e >> 3;
        int c = e & 7;
        cp16(sw_addr(sbase, r, c), (const void*)(g + (size_t)r * ld + c * 8));
    }
}

__device__ __forceinline__ void load_stage(uint32_t st,
    const __half* gAh, const __half* gAl, const __half* gB,
    int kk, int K, int tid)
{
    load_tileN<4>(st,                    gAh + kk, K, tid);
    load_tileN<4>(st + TILE_A_BYTES,     gAl + kk, K, tid);
    load_tileN<2>(st + 2 * TILE_A_BYTES, gB + kk, K, tid);
    asm volatile("cp.async.commit_group;" ::: "memory");
}

__global__ __launch_bounds__(GEMM_THREADS, 1) void gemm_f16split_kernel(
    const __half* __restrict__ Ah, const __half* __restrict__ Al,
    const __half* __restrict__ B, float* __restrict__ C, int M, int N, int K)
{
    extern __shared__ char smem[];
    uint32_t sb = smem_u32(smem);
    int tid = threadIdx.x;
    int warp = tid >> 5, lane = tid & 31;
    int row0 = blockIdx.y * GEMM_BM;
    int col0 = blockIdx.x * GEMM_BN;
    int wm0 = (warp >> 2) * 64;
    int wn0 = (warp & 3) * 32;

    const __half* gAh = Ah + (size_t)row0 * K;
    const __half* gAl = Al + (size_t)row0 * K;
    const __half* gB  = B  + (size_t)col0 * K;

    const int T = K / GEMM_BK;

    float acc[4][4][4];
#pragma unroll
    for (int m = 0; m < 4; m++)
#pragma unroll
        for (int n = 0; n < 4; n++)
#pragma unroll
            for (int f = 0; f < 4; f++) acc[m][n][f] = 0.f;

    load_stage(sb,               gAh, gAl, gB, 0,       K, tid);
    load_stage(sb + STAGE_BYTES, gAh, gAl, gB, GEMM_BK, K, tid);

    int mat = lane >> 3;
    int frow = (lane & 7) + ((mat & 1) << 3);
    int fch  = mat >> 1;

    for (int t = 0; t < T; t++) {
        if (t == T - 1) asm volatile("cp.async.wait_group 0;" ::: "memory");
        else            asm volatile("cp.async.wait_group 1;" ::: "memory");
        __syncthreads();

        uint32_t st = sb + (t & 1) * STAGE_BYTES;
        uint32_t sAh = st, sAl = st + TILE_A_BYTES;
        uint32_t sB  = st + 2 * TILE_A_BYTES;

#pragma unroll
        for (int ks = 0; ks < 4; ks++) {
            int kc = ks * 2 + fch;
            uint32_t bf[2][4];
#pragma unroll
            for (int g = 0; g < 2; g++) {
                int brow = wn0 + g * 16 + frow;
                ldsm_x4(bf[g], sw_addr(sB, brow, kc));
            }
#pragma unroll
            for (int m = 0; m < 4; m++) {
                int arow = wm0 + m * 16 + frow;
                uint32_t ah[4], al[4];
                ldsm_x4(ah, sw_addr(sAh, arow, kc));
                ldsm_x4(al, sw_addr(sAl, arow, kc));
#pragma unroll
                for (int n = 0; n < 4; n++) {
                    int g = n >> 1, h = n & 1;
                    uint32_t bff[2] = {bf[g][h], bf[g][h + 2]};
                    mma16816(acc[m][n], ah, bff);
                    mma16816(acc[m][n], al, bff);
                }
            }
        }
        __syncthreads();

        if (t + 2 < T)
            load_stage(st, gAh, gAl, gB, (t + 2) * GEMM_BK, K, tid);
    }

#pragma unroll
    for (int m = 0; m < 4; m++) {
        int r0 = row0 + wm0 + m * 16 + (lane >> 2);
#pragma unroll
        for (int n = 0; n < 4; n++) {
            int c = col0 + wn0 + n * 8 + (lane & 3) * 2;
            *(float2*)&C[(size_t)r0 * N + c]       = make_float2(acc[m][n][0], acc[m][n][1]);
            *(float2*)&C[(size_t)(r0 + 8) * N + c] = make_float2(acc[m][n][2], acc[m][n][3]);
        }
    }
}

// ---------------- single-term fp16 GEMM, half output (V projection) ----------------
__device__ __forceinline__ void load_stage1(uint32_t st,
    const __half* gA, const __half* gB, int kk, int K, int tid)
{
    load_tileN<4>(st,                gA + kk, K, tid);
    load_tileN<2>(st + TILE_A_BYTES, gB + kk, K, tid);
    asm volatile("cp.async.commit_group;" ::: "memory");
}

__global__ __launch_bounds__(GEMM_THREADS, 1) void gemm_f16single_kernel(
    const __half* __restrict__ A, const __half* __restrict__ B,
    __half* __restrict__ C, int M, int N, int K)
{
    extern __shared__ char smem[];
    uint32_t sb = smem_u32(smem);
    int tid = threadIdx.x;
    int warp = tid >> 5, lane = tid & 31;
    int row0 = blockIdx.y * GEMM_BM;
    int col0 = blockIdx.x * GEMM_BN;
    int wm0 = (warp >> 2) * 64;
    int wn0 = (warp & 3) * 32;

    const __half* gA = A + (size_t)row0 * K;
    const __half* gB = B + (size_t)col0 * K;
    const int T = K / GEMM_BK;

    float acc[4][4][4];
#pragma unroll
    for (int m = 0; m < 4; m++)
#pragma unroll
        for (int n = 0; n < 4; n++)
#pragma unroll
            for (int f = 0; f < 4; f++) acc[m][n][f] = 0.f;

    load_stage1(sb,                gA, gB, 0,       K, tid);
    load_stage1(sb + STAGE1_BYTES, gA, gB, GEMM_BK, K, tid);

    int mat = lane >> 3;
    int frow = (lane & 7) + ((mat & 1) << 3);
    int fch  = mat >> 1;

    for (int t = 0; t < T; t++) {
        if (t == T - 1) asm volatile("cp.async.wait_group 0;" ::: "memory");
        else            asm volatile("cp.async.wait_group 1;" ::: "memory");
        __syncthreads();

        uint32_t st = sb + (t & 1) * STAGE1_BYTES;
        uint32_t sA = st, sB = st + TILE_A_BYTES;

#pragma unroll
        for (int ks = 0; ks < 4; ks++) {
            int kc = ks * 2 + fch;
            uint32_t bf[2][4];
#pragma unroll
            for (int g = 0; g < 2; g++) {
                int brow = wn0 + g * 16 + frow;
                ldsm_x4(bf[g], sw_addr(sB, brow, kc));
            }
#pragma unroll
            for (int m = 0; m < 4; m++) {
                int arow = wm0 + m * 16 + frow;
                uint32_t a[4];
                ldsm_x4(a, sw_addr(sA, arow, kc));
#pragma unroll
                for (int n = 0; n < 4; n++) {
                    int g = n >> 1, h = n & 1;
                    uint32_t bff[2] = {bf[g][h], bf[g][h + 2]};
                    mma16816(acc[m][n], a, bff);
                }
            }
        }
        __syncthreads();

        if (t + 2 < T)
            load_stage1(st, gA, gB, (t + 2) * GEMM_BK, K, tid);
    }

#pragma unroll
    for (int m = 0; m < 4; m++) {
        int r0 = row0 + wm0 + m * 16 + (lane >> 2);
#pragma unroll
        for (int n = 0; n < 4; n++) {
            int c = col0 + wn0 + n * 8 + (lane & 3) * 2;
            __half2 h0 = __floats2half2_rn(acc[m][n][0], acc[m][n][1]);
            __half2 h1 = __floats2half2_rn(acc[m][n][2], acc[m][n][3]);
            *(__half2*)&C[(size_t)r0 * N + c]       = h0;
            *(__half2*)&C[(size_t)(r0 + 8) * N + c] = h1;
        }
    }
}

// ---------------- per-head RMSNorm + RoPE -> fp16 ----------------
__global__ __launch_bounds__(128) void rmsnorm_rope_f16_kernel(
    const float* __restrict__ X, const float* __restrict__ w,
    __half* __restrict__ Y, int n_heads, float osc)
{
    int row = blockIdx.x;
    int t = (row / n_heads) % TT;
    int d = threadIdx.x;
    const float* xr = X + (size_t)row * HD;

    float v = xr[d];
    float s = v * v;
#pragma unroll
    for (int off = 16; off; off >>= 1) s += __shfl_xor_sync(0xffffffffu, s, off);

    __shared__ float red[4];
    __shared__ float xs[HD];
    int warp = d >> 5, lane = d & 31;
    if (lane == 0) red[warp] = s;
    __syncthreads();
    float tot = red[0] + red[1] + red[2] + red[3];
    float rinv = rsqrtf(tot * (1.0f / HD) + 1e-6f);
    xs[d] = w[d] * v * rinv;
    __syncthreads();

    if (d < 64) {
        float a = xs[d];
        float b = xs[d + 64];
        double freq = pow(1.0e6, -(double)(2 * d) / 128.0);
        double ang = (double)t * freq;
        double sn, cs;
        sincos(ang, &sn, &cs);
        float fs = (float)sn, fc = (float)cs;
        __half* yr = Y + (size_t)row * HD;
        yr[d]      = __float2half((a * fc - b * fs) * osc);
        yr[d + 64] = __float2half((b * fc + a * fs) * osc);
    }
}

// ---------------- fp16 tensor-core causal GQA flash attention (v2) ----------------
// fp16 inputs (Q pre-scaled), cp.async double-buffered K/V, fp16 hi/lo output.
// CTA: 128 threads (4 warps). Tile 64(q) x 64(k), D=128.
// smem: Q 16KB + 2 stages x (K 16KB + V 16KB) = 80KB.
#define FL_SMEM (5 * 64 * 256)

__device__ __forceinline__ uint32_t fl_addr(uint32_t base, int row, int chunk) {
    return base + row * 256 + ((chunk ^ (row & 7)) << 4);
}

__device__ __forceinline__ void fl_load_kv(uint32_t sK, uint32_t sV,
    const __half* Kp, const __half* Vp, int tid)
{
#pragma unroll
    for (int i = 0; i < 8; i++) {
        int e = tid + i * 128;
        int r = e >> 4, c = e & 15;
        cp16(fl_addr(sK, r, c), Kp + (size_t)r * NKVD + c * 8);
        cp16(fl_addr(sV, r, c), Vp + (size_t)r * NKVD + c * 8);
    }
}

__global__ __launch_bounds__(128) void flash16_kernel(
    const __half* __restrict__ Q, const __half* __restrict__ Kb,
    const __half* __restrict__ Vb, __half* __restrict__ Oh,
    __half* __restrict__ Ol)
{
    extern __shared__ char sm[];
    uint32_t sQ = smem_u32(sm);
    uint32_t sKV = sQ + 64 * 256;      // stage s: K at sKV + s*32KB, V at +16KB

    int tid = threadIdx.x, warp = tid >> 5, lane = tid & 31;
    int qt0 = blockIdx.x * 64;
    int h = blockIdx.y;
    int b = blockIdx.z;
    int kvh = h / GROUPS;

    const __half* Qp = Q + ((size_t)(b * TT + qt0) * NH + h) * HD;
    const __half* Kp0 = Kb + ((size_t)b * TT * NKV + kvh) * HD;
    const __half* Vp0 = Vb + ((size_t)b * TT * NKV + kvh) * HD;

    // prologue: Q + KV tile 0
#pragma unroll
    for (int i = 0; i < 8; i++) {
        int e = tid + i * 128;
        int r = e >> 4, c = e & 15;
        cp16(fl_addr(sQ, r, c), Qp + (size_t)r * NQ + c * 8);
    }
    fl_load_kv(sKV, sKV + 64 * 256, Kp0, Vp0, tid);
    asm volatile("cp.async.commit_group;" ::: "memory");

    float m_lo = -1e30f, m_hi = -1e30f;
    float l_lo = 0.f, l_hi = 0.f;
    float acc[16][4];
#pragma unroll
    for (int g = 0; g < 16; g++)
#pragma unroll
        for (int f = 0; f < 4; f++) acc[g][f] = 0.f;

    int m0 = warp * 16;
    int lrow = lane & 15;
    int lch  = lane >> 4;

    int n_kt = qt0 / 64 + 1;
    for (int kt = 0; kt < n_kt; kt++) {
        if (kt + 1 < n_kt) {
            uint32_t st = sKV + ((kt + 1) & 1) * (2 * 64 * 256);
            fl_load_kv(st, st + 64 * 256,
                       Kp0 + (size_t)(kt + 1) * 64 * NKVD,
                       Vp0 + (size_t)(kt + 1) * 64 * NKVD, tid);
            asm volatile("cp.async.commit_group;" ::: "memory");
            asm volatile("cp.async.wait_group 1;" ::: "memory");
        } else {
            asm volatile("cp.async.wait_group 0;" ::: "memory");
        }
        __syncthreads();

        uint32_t sK = sKV + (kt & 1) * (2 * 64 * 256);
        uint32_t sV = sK + 64 * 256;

        // ---- S = Q_warp @ K^T ----
        float sacc[8][4];
#pragma unroll
        for (int n = 0; n < 8; n++)
#pragma unroll
            for (int f = 0; f < 4; f++) sacc[n][f] = 0.f;

#pragma unroll
        for (int ks = 0; ks < 8; ks++) {
            uint32_t a[4];
            ldsm_x4(a, fl_addr(sQ, m0 + lrow, 2 * ks + lch));
#pragma unroll
            for (int g = 0; g < 4; g++) {
                uint32_t kf[4];
                ldsm_x4(kf, fl_addr(sK, g * 16 + lrow, 2 * ks + lch));
                uint32_t b0[2] = {kf[0], kf[2]};
                uint32_t b1[2] = {kf[1], kf[3]};
                mma16816(sacc[2 * g],     a, b0);
                mma16816(sacc[2 * g + 1], a, b1);
            }
        }

        // ---- causal mask (diagonal tile only) ----
        if (kt == n_kt - 1) {
            int r_lo = m0 + (lane >> 2);
            int r_hi = r_lo + 8;
            int cbase = (lane & 3) * 2;
#pragma unroll
            for (int n = 0; n < 8; n++) {
                int c0 = n * 8 + cbase, c1 = c0 + 1;
                if (c0 > r_lo) sacc[n][0] = -1e30f;
                if (c1 > r_lo) sacc[n][1] = -1e30f;
                if (c0 > r_hi) sacc[n][2] = -1e30f;
                if (c1 > r_hi) sacc[n][3] = -1e30f;
            }
        }

        // ---- online softmax ----
        float mx_lo = -1e30f, mx_hi = -1e30f;
#pragma unroll
        for (int n = 0; n < 8; n++) {
            mx_lo = fmaxf(mx_lo, fmaxf(sacc[n][0], sacc[n][1]));
            mx_hi = fmaxf(mx_hi, fmaxf(sacc[n][2], sacc[n][3]));
        }
#pragma unroll
        for (int off = 1; off <= 2; off <<= 1) {
            mx_lo = fmaxf(mx_lo, __shfl_xor_sync(0xffffffffu, mx_lo, off));
            mx_hi = fmaxf(mx_hi, __shfl_xor_sync(0xffffffffu, mx_hi, off));
        }
        float mn_lo = fmaxf(m_lo, mx_lo);
        float mn_hi = fmaxf(m_hi, mx_hi);
        float sum_lo = 0.f, sum_hi = 0.f;
#pragma unroll
        for (int n = 0; n < 8; n++) {
            sacc[n][0] = expf(sacc[n][0] - mn_lo);
            sacc[n][1] = expf(sacc[n][1] - mn_lo);
            sacc[n][2] = expf(sacc[n][2] - mn_hi);
            sacc[n][3] = expf(sacc[n][3] - mn_hi);
            sum_lo += sacc[n][0] + sacc[n][1];
            sum_hi += sacc[n][2] + sacc[n][3];
        }
#pragma unroll
        for (int off = 1; off <= 2; off <<= 1) {
            sum_lo += __shfl_xor_sync(0xffffffffu, sum_lo, off);
            sum_hi += __shfl_xor_sync(0xffffffffu, sum_hi, off);
        }
        float al_lo = expf(m_lo - mn_lo);
        float al_hi = expf(m_hi - mn_hi);
        l_lo = l_lo * al_lo + sum_lo;  m_lo = mn_lo;
        l_hi = l_hi * al_hi + sum_hi;  m_hi = mn_hi;
#pragma unroll
        for (int g = 0; g < 16; g++) {
            acc[g][0] *= al_lo; acc[g][1] *= al_lo;
            acc[g][2] *= al_hi; acc[g][3] *= al_hi;
        }

        // ---- pack P fragments ----
        uint32_t pf[4][4];
#pragma unroll
        for (int j = 0; j < 4; j++) {
            __half2 p0 = __floats2half2_rn(sacc[2*j][0],   sacc[2*j][1]);
            __half2 p1 = __floats2half2_rn(sacc[2*j][2],   sacc[2*j][3]);
            __half2 p2 = __floats2half2_rn(sacc[2*j+1][0], sacc[2*j+1][1]);
            __half2 p3 = __floats2half2_rn(sacc[2*j+1][2], sacc[2*j+1][3]);
            pf[j][0] = *(uint32_t*)&p0;
            pf[j][1] = *(uint32_t*)&p1;
            pf[j][2] = *(uint32_t*)&p2;
            pf[j][3] = *(uint32_t*)&p3;
        }

        // ---- O += P @ V ----
        int vrow_off = (lane & 7) + ((lane >> 3) & 1) * 8;
#pragma unroll
        for (int j = 0; j < 4; j++) {
            int c0 = j * 16;
#pragma unroll
            for (int g = 0; g < 8; g++) {
                uint32_t vf[4];
                ldsm_x4_t(vf, fl_addr(sV, c0 + vrow_off, 2 * g + lch));
                uint32_t b0[2] = {vf[0], vf[1]};
                uint32_t b1[2] = {vf[2], vf[3]};
                mma16816(acc[2 * g],     pf[j], b0);
                mma16816(acc[2 * g + 1], pf[j], b1);
            }
        }
        __syncthreads();   // all warps done with this stage before refill
    }

    // ---- epilogue: fp16 hi/lo split output ----
    float inv_lo = 1.f / l_lo, inv_hi = 1.f / l_hi;
    int r_lo = qt0 + m0 + (lane >> 2);
    int r_hi = r_lo + 8;
    size_t base_lo = (size_t)(b * TT + r_lo) * NQ + h * HD;
    size_t base_hi = (size_t)(b * TT + r_hi) * NQ + h * HD;
#pragma unroll
    for (int g = 0; g < 16; g++) {
        int d = g * 8 + (lane & 3) * 2;
        float o0 = acc[g][0] * inv_lo, o1 = acc[g][1] * inv_lo;
        float o2 = acc[g][2] * inv_hi, o3 = acc[g][3] * inv_hi;
        __half h0 = __float2half(o0), h1 = __float2half(o1);
        __half h2 = __float2half(o2), h3 = __float2half(o3);
        *(__half2*)&Oh[base_lo + d] = __halves2half2(h0, h1);
        *(__half2*)&Oh[base_hi + d] = __halves2half2(h2, h3);
        *(__half2*)&Ol[base_lo + d] = __floats2half2_rn(o0 - __half2float(h0),
                                                        o1 - __half2float(h1));
        *(__half2*)&Ol[base_hi + d] = __floats2half2_rn(o2 - __half2float(h2),
                                                        o3 - __half2float(h3));
    }
}

// ---------------- launch ----------------
extern "C" void kernel_launch(void* const* d_in, const int* in_sizes, int n_in,
                              void* d_out, int out_size)
{
    const float* x   = (const float*)d_in[0];
    const float* wq  = (const float*)d_in[1];
    const float* wk  = (const float*)d_in[2];
    const float* wv  = (const float*)d_in[3];
    const float* wo  = (const float*)d_in[4];
    const float* qnw = (const float*)d_in[5];
    const float* knw = (const float*)d_in[6];
    float* out = (float*)d_out;

    __half *xh, *xl, *wqt, *wkt, *wvt, *wot, *ah, *al, *q16, *k16, *v16;
    float *qb, *kb;
    cudaGetSymbolAddress((void**)&xh, g_xh);   cudaGetSymbolAddress((void**)&xl, g_xl);
    cudaGetSymbolAddress((void**)&wqt, g_wqt); cudaGetSymbolAddress((void**)&wkt, g_wkt);
    cudaGetSymbolAddress((void**)&wvt, g_wvt); cudaGetSymbolAddress((void**)&wot, g_wot);
    cudaGetSymbolAddress((void**)&ah, g_ah);   cudaGetSymbolAddress((void**)&al, g_al);
    cudaGetSymbolAddress((void**)&qb, g_q);    cudaGetSymbolAddress((void**)&kb, g_k);
    cudaGetSymbolAddress((void**)&q16, g_q16); cudaGetSymbolAddress((void**)&k16, g_k16);
    cudaGetSymbolAddress((void**)&v16, g_v16);

    // split x (fp16 hi/lo), transpose weights to fp16 [N,K]
    convert_split_kernel<<<(MROWS * HID + 255) / 256, 256>>>(x, xh, xl, MROWS * HID);
    transpose_f16_kernel<<<dim3(NQ / 32, HID / 32), dim3(32, 8)>>>(wq, wqt, HID, NQ);
    transpose_f16_kernel<<<dim3(NKVD / 32, HID / 32), dim3(32, 8)>>>(wk, wkt, HID, NKVD);
    transpose_f16_kernel<<<dim3(NKVD / 32, HID / 32), dim3(32, 8)>>>(wv, wvt, HID, NKVD);
    transpose_f16_kernel<<<dim3(HID / 32, NQ / 32), dim3(32, 8)>>>(wo, wot, NQ, HID);

    cudaFuncSetAttribute(gemm_f16split_kernel,
                         cudaFuncAttributeMaxDynamicSharedMemorySize, GEMM_SMEM);
    cudaFuncSetAttribute(gemm_f16single_kernel,
                         cudaFuncAttributeMaxDynamicSharedMemorySize, GEMM1_SMEM);

    // Q/K projections (2-term, fp32 out); V projection (1-term, fp16 out)
    gemm_f16split_kernel<<<dim3(NQ / GEMM_BN, MROWS / GEMM_BM), GEMM_THREADS, GEMM_SMEM>>>(
        xh, xl, wqt, qb, MROWS, NQ, HID);
    gemm_f16split_kernel<<<dim3(NKVD / GEMM_BN, MROWS / GEMM_BM), GEMM_THREADS, GEMM_SMEM>>>(
        xh, xl, wkt, kb, MROWS, NKVD, HID);
    gemm_f16single_kernel<<<dim3(NKVD / GEMM_BN, MROWS / GEMM_BM), GEMM_THREADS, GEMM1_SMEM>>>(
        xh, wvt, v16, MROWS, NKVD, HID);

    // per-head RMSNorm + RoPE -> fp16 (Q pre-scaled by 1/sqrt(HD))
    rmsnorm_rope_f16_kernel<<<MROWS * NH, 128>>>(qb, qnw, q16, NH, 0.08838834764831845f);
    rmsnorm_rope_f16_kernel<<<MROWS * NKV, 128>>>(kb, knw, k16, NKV, 1.0f);

    // flash attention (fp16 in/out, pipelined K/V)
    cudaFuncSetAttribute(flash16_kernel, cudaFuncAttributeMaxDynamicSharedMemorySize, FL_SMEM);
    flash16_kernel<<<dim3(TT / 64, NH, BB), 128, FL_SMEM>>>(q16, k16, v16, ah, al);

    // output projection (2-term, reads flash's hi/lo output directly)
    gemm_f16split_kernel<<<dim3(HID / GEMM_BN, MROWS / GEMM_BM), GEMM_THREADS, GEMM_SMEM>>>(
        ah, al, wot, out, MROWS, HID, NQ);
}

// round 8
// speedup vs baseline: 2.6094x; 1.2214x over previous
#include <cuda_runtime.h>
#include <cuda_fp16.h>
#include <math.h>
#include <stdint.h>

// ---------------- problem constants ----------------
#define BB    2
#define TT    2048
#define HID   4096
#define NH    32
#define NKV   8
#define HD    128
#define MROWS (BB*TT)      // 4096
#define NQ    (NH*HD)      // 4096
#define NKVD  (NKV*HD)     // 1024
#define GROUPS (NH/NKV)    // 4

// ---------------- scratch (device globals, no allocation) ----------------
__device__ __half g_x16[(size_t)MROWS * HID];
__device__ __half g_wqt[(size_t)NQ * HID];
__device__ __half g_wkt[(size_t)NKVD * HID];
__device__ __half g_wvt[(size_t)NKVD * HID];
__device__ __half g_wot[(size_t)HID * NQ];
__device__ __half g_attn16[(size_t)MROWS * NQ];
__device__ float g_q[(size_t)MROWS * NQ];
__device__ float g_k[(size_t)MROWS * NKVD];
__device__ __half g_q16[(size_t)MROWS * NQ];
__device__ __half g_k16[(size_t)MROWS * NKVD];
__device__ __half g_v16[(size_t)MROWS * NKVD];

// ---------------- PTX helpers (base ISA only) ----------------
__device__ __forceinline__ uint32_t smem_u32(const void* p) {
    uint32_t a;
    asm("{ .reg .u64 t; cvta.to.shared.u64 t, %1; cvt.u32.u64 %0, t; }" : "=r"(a) : "l"(p));
    return a;
}

__device__ __forceinline__ void cp16(uint32_t dst, const void* src) {
    asm volatile("cp.async.cg.shared.global [%0], [%1], 16;" :: "r"(dst), "l"(src));
}

__device__ __forceinline__ void ldsm_x4(uint32_t* r, uint32_t addr) {
    asm volatile("ldmatrix.sync.aligned.m8n8.x4.shared.b16 {%0,%1,%2,%3}, [%4];"
                 : "=r"(r[0]), "=r"(r[1]), "=r"(r[2]), "=r"(r[3]) : "r"(addr));
}

__device__ __forceinline__ void ldsm_x4_t(uint32_t* r, uint32_t addr) {
    asm volatile("ldmatrix.sync.aligned.m8n8.x4.trans.shared.b16 {%0,%1,%2,%3}, [%4];"
                 : "=r"(r[0]), "=r"(r[1]), "=r"(r[2]), "=r"(r[3]) : "r"(addr));
}

__device__ __forceinline__ void mma16816(float* d, const uint32_t* a, const uint32_t* b) {
    asm volatile(
        "mma.sync.aligned.m16n8k16.row.col.f32.f16.f16.f32 "
        "{%0,%1,%2,%3}, {%4,%5,%6,%7}, {%8,%9}, {%0,%1,%2,%3};"
        : "+f"(d[0]), "+f"(d[1]), "+f"(d[2]), "+f"(d[3])
        : "r"(a[0]), "r"(a[1]), "r"(a[2]), "r"(a[3]), "r"(b[0]), "r"(b[1]));
}

// ---------------- convert kernels ----------------
__global__ __launch_bounds__(256) void convert_f16_kernel(
    const float* __restrict__ in, __half* __restrict__ o, int n)
{
    int i = blockIdx.x * blockDim.x + threadIdx.x;
    if (i < n) o[i] = __float2half(in[i]);
}

__global__ __launch_bounds__(256) void transpose_f16_kernel(
    const float* __restrict__ in, __half* __restrict__ o, int R, int C)
{
    __shared__ float t[32][33];
    int bx = blockIdx.x * 32;   // C
    int by = blockIdx.y * 32;   // R
    int tx = threadIdx.x, ty = threadIdx.y;   // 32 x 8
#pragma unroll
    for (int j = 0; j < 32; j += 8)
        t[ty + j][tx] = in[(size_t)(by + ty + j) * C + bx + tx];
    __syncthreads();
#pragma unroll
    for (int j = 0; j < 32; j += 8)
        o[(size_t)(bx + ty + j) * R + by + tx] = __float2half(t[tx][ty + j]);
}

// ---------------- mma.sync single-term fp16 GEMM ----------------
// C[M,N] = A@B^T.  A:[M,K] fp16; B:[N,K] fp16 (pre-transposed).
// CTA 256x128, BK=64, 16 warps (4x4), warp tile 64x32, 2-stage cp.async.
#define GEMM_BM 256
#define GEMM_BN 128
#define GEMM_BK 64
#define GEMM_THREADS 512
#define TILE_A_BYTES (GEMM_BM * GEMM_BK * 2)   // 32 KB
#define TILE_B_BYTES (GEMM_BN * GEMM_BK * 2)   // 16 KB
#define STAGE_BYTES (TILE_A_BYTES + TILE_B_BYTES)  // 48 KB
#define GEMM_SMEM (2 * STAGE_BYTES)            // 96 KB

__device__ __forceinline__ uint32_t sw_addr(uint32_t base, int row, int chunk) {
    return base + row * 128 + ((chunk ^ (row & 7)) << 4);
}

template<int ITER>
__device__ __forceinline__ void load_tileN(uint32_t sbase, const __half* g,
                                           int ld, int tid)
{
#pragma unroll
    for (int i = 0; i < ITER; i++) {
        int e = tid + i * GEMM_THREADS;
        int r = e >> 3;
        int c = e & 7;
        cp16(sw_addr(sbase, r, c), (const void*)(g + (size_t)r * ld + c * 8));
    }
}

__device__ __forceinline__ void load_stage(uint32_t st,
    const __half* gA, const __half* gB, int kk, int K, int tid)
{
    load_tileN<4>(st,                gA + kk, K, tid);
    load_tileN<2>(st + TILE_A_BYTES, gB + kk, K, tid);
    asm volatile("cp.async.commit_group;" ::: "memory");
}

__device__ __forceinline__ void store2(float* p, float a, float b) {
    *(float2*)p = make_float2(a, b);
}
__device__ __forceinline__ void store2(__half* p, float a, float b) {
    *(__half2*)p = __floats2half2_rn(a, b);
}

template<typename OutT>
__global__ __launch_bounds__(GEMM_THREADS, 1) void gemm_f16_kernel(
    const __half* __restrict__ A, const __half* __restrict__ B,
    OutT* __restrict__ C, int M, int N, int K)
{
    extern __shared__ char smem[];
    uint32_t sb = smem_u32(smem);
    int tid = threadIdx.x;
    int warp = tid >> 5, lane = tid & 31;
    int row0 = blockIdx.y * GEMM_BM;
    int col0 = blockIdx.x * GEMM_BN;
    int wm0 = (warp >> 2) * 64;
    int wn0 = (warp & 3) * 32;

    const __half* gA = A + (size_t)row0 * K;
    const __half* gB = B + (size_t)col0 * K;
    const int T = K / GEMM_BK;

    float acc[4][4][4];
#pragma unroll
    for (int m = 0; m < 4; m++)
#pragma unroll
        for (int n = 0; n < 4; n++)
#pragma unroll
            for (int f = 0; f < 4; f++) acc[m][n][f] = 0.f;

    load_stage(sb,               gA, gB, 0,       K, tid);
    load_stage(sb + STAGE_BYTES, gA, gB, GEMM_BK, K, tid);

    int mat = lane >> 3;
    int frow = (lane & 7) + ((mat & 1) << 3);
    int fch  = mat >> 1;

    for (int t = 0; t < T; t++) {
        if (t == T - 1) asm volatile("cp.async.wait_group 0;" ::: "memory");
        else            asm volatile("cp.async.wait_group 1;" ::: "memory");
        __syncthreads();

        uint32_t st = sb + (t & 1) * STAGE_BYTES;
        uint32_t sA = st, sB = st + TILE_A_BYTES;

#pragma unroll
        for (int ks = 0; ks < 4; ks++) {
            int kc = ks * 2 + fch;
            uint32_t bf[2][4];
#pragma unroll
            for (int g = 0; g < 2; g++) {
                int brow = wn0 + g * 16 + frow;
                ldsm_x4(bf[g], sw_addr(sB, brow, kc));
            }
#pragma unroll
            for (int m = 0; m < 4; m++) {
                int arow = wm0 + m * 16 + frow;
                uint32_t a[4];
                ldsm_x4(a, sw_addr(sA, arow, kc));
#pragma unroll
                for (int n = 0; n < 4; n++) {
                    int g = n >> 1, h = n & 1;
                    uint32_t bff[2] = {bf[g][h], bf[g][h + 2]};
                    mma16816(acc[m][n], a, bff);
                }
            }
        }
        __syncthreads();

        if (t + 2 < T)
            load_stage(st, gA, gB, (t + 2) * GEMM_BK, K, tid);
    }

#pragma unroll
    for (int m = 0; m < 4; m++) {
        int r0 = row0 + wm0 + m * 16 + (lane >> 2);
#pragma unroll
        for (int n = 0; n < 4; n++) {
            int c = col0 + wn0 + n * 8 + (lane & 3) * 2;
            store2(&C[(size_t)r0 * N + c],       acc[m][n][0], acc[m][n][1]);
            store2(&C[(size_t)(r0 + 8) * N + c], acc[m][n][2], acc[m][n][3]);
        }
    }
}

// ---------------- per-head RMSNorm + RoPE -> fp16 ----------------
__global__ __launch_bounds__(128) void rmsnorm_rope_f16_kernel(
    const float* __restrict__ X, const float* __restrict__ w,
    __half* __restrict__ Y, int n_heads, float osc)
{
    int row = blockIdx.x;
    int t = (row / n_heads) % TT;
    int d = threadIdx.x;
    const float* xr = X + (size_t)row * HD;

    float v = xr[d];
    float s = v * v;
#pragma unroll
    for (int off = 16; off; off >>= 1) s += __shfl_xor_sync(0xffffffffu, s, off);

    __shared__ float red[4];
    __shared__ float xs[HD];
    int warp = d >> 5, lane = d & 31;
    if (lane == 0) red[warp] = s;
    __syncthreads();
    float tot = red[0] + red[1] + red[2] + red[3];
    float rinv = rsqrtf(tot * (1.0f / HD) + 1e-6f);
    xs[d] = w[d] * v * rinv;
    __syncthreads();

    if (d < 64) {
        float a = xs[d];
        float b = xs[d + 64];
        double freq = pow(1.0e6, -(double)(2 * d) / 128.0);
        double ang = (double)t * freq;
        double sn, cs;
        sincos(ang, &sn, &cs);
        float fs = (float)sn, fc = (float)cs;
        __half* yr = Y + (size_t)row * HD;
        yr[d]      = __float2half((a * fc - b * fs) * osc);
        yr[d + 64] = __float2half((b * fc + a * fs) * osc);
    }
}

// ---------------- fp16 tensor-core causal GQA flash attention ----------------
// fp16 in/out (Q pre-scaled), cp.async double-buffered K/V.
// CTA: 128 threads (4 warps). Tile 64(q) x 64(k), D=128. smem 80 KB.
#define FL_SMEM (5 * 64 * 256)

__device__ __forceinline__ uint32_t fl_addr(uint32_t base, int row, int chunk) {
    return base + row * 256 + ((chunk ^ (row & 7)) << 4);
}

__device__ __forceinline__ void fl_load_kv(uint32_t sK, uint32_t sV,
    const __half* Kp, const __half* Vp, int tid)
{
#pragma unroll
    for (int i = 0; i < 8; i++) {
        int e = tid + i * 128;
        int r = e >> 4, c = e & 15;
        cp16(fl_addr(sK, r, c), Kp + (size_t)r * NKVD + c * 8);
        cp16(fl_addr(sV, r, c), Vp + (size_t)r * NKVD + c * 8);
    }
}

__global__ __launch_bounds__(128) void flash16_kernel(
    const __half* __restrict__ Q, const __half* __restrict__ Kb,
    const __half* __restrict__ Vb, __half* __restrict__ O)
{
    extern __shared__ char sm[];
    uint32_t sQ = smem_u32(sm);
    uint32_t sKV = sQ + 64 * 256;

    int tid = threadIdx.x, warp = tid >> 5, lane = tid & 31;
    int qt0 = blockIdx.x * 64;
    int h = blockIdx.y;
    int b = blockIdx.z;
    int kvh = h / GROUPS;

    const __half* Qp = Q + ((size_t)(b * TT + qt0) * NH + h) * HD;
    const __half* Kp0 = Kb + ((size_t)b * TT * NKV + kvh) * HD;
    const __half* Vp0 = Vb + ((size_t)b * TT * NKV + kvh) * HD;

#pragma unroll
    for (int i = 0; i < 8; i++) {
        int e = tid + i * 128;
        int r = e >> 4, c = e & 15;
        cp16(fl_addr(sQ, r, c), Qp + (size_t)r * NQ + c * 8);
    }
    fl_load_kv(sKV, sKV + 64 * 256, Kp0, Vp0, tid);
    asm volatile("cp.async.commit_group;" ::: "memory");

    float m_lo = -1e30f, m_hi = -1e30f;
    float l_lo = 0.f, l_hi = 0.f;
    float acc[16][4];
#pragma unroll
    for (int g = 0; g < 16; g++)
#pragma unroll
        for (int f = 0; f < 4; f++) acc[g][f] = 0.f;

    int m0 = warp * 16;
    int lrow = lane & 15;
    int lch  = lane >> 4;

    int n_kt = qt0 / 64 + 1;
    for (int kt = 0; kt < n_kt; kt++) {
        if (kt + 1 < n_kt) {
            uint32_t st = sKV + ((kt + 1) & 1) * (2 * 64 * 256);
            fl_load_kv(st, st + 64 * 256,
                       Kp0 + (size_t)(kt + 1) * 64 * NKVD,
                       Vp0 + (size_t)(kt + 1) * 64 * NKVD, tid);
            asm volatile("cp.async.commit_group;" ::: "memory");
            asm volatile("cp.async.wait_group 1;" ::: "memory");
        } else {
            asm volatile("cp.async.wait_group 0;" ::: "memory");
        }
        __syncthreads();

        uint32_t sK = sKV + (kt & 1) * (2 * 64 * 256);
        uint32_t sV = sK + 64 * 256;

        // ---- S = Q_warp @ K^T ----
        float sacc[8][4];
#pragma unroll
        for (int n = 0; n < 8; n++)
#pragma unroll
            for (int f = 0; f < 4; f++) sacc[n][f] = 0.f;

#pragma unroll
        for (int ks = 0; ks < 8; ks++) {
            uint32_t a[4];
            ldsm_x4(a, fl_addr(sQ, m0 + lrow, 2 * ks + lch));
#pragma unroll
            for (int g = 0; g < 4; g++) {
                uint32_t kf[4];
                ldsm_x4(kf, fl_addr(sK, g * 16 + lrow, 2 * ks + lch));
                uint32_t b0[2] = {kf[0], kf[2]};
                uint32_t b1[2] = {kf[1], kf[3]};
                mma16816(sacc[2 * g],     a, b0);
                mma16816(sacc[2 * g + 1], a, b1);
            }
        }

        // ---- causal mask (diagonal tile only) ----
        if (kt == n_kt - 1) {
            int r_lo = m0 + (lane >> 2);
            int r_hi = r_lo + 8;
            int cbase = (lane & 3) * 2;
#pragma unroll
            for (int n = 0; n < 8; n++) {
                int c0 = n * 8 + cbase, c1 = c0 + 1;
                if (c0 > r_lo) sacc[n][0] = -1e30f;
                if (c1 > r_lo) sacc[n][1] = -1e30f;
                if (c0 > r_hi) sacc[n][2] = -1e30f;
                if (c1 > r_hi) sacc[n][3] = -1e30f;
            }
        }

        // ---- online softmax ----
        float mx_lo = -1e30f, mx_hi = -1e30f;
#pragma unroll
        for (int n = 0; n < 8; n++) {
            mx_lo = fmaxf(mx_lo, fmaxf(sacc[n][0], sacc[n][1]));
            mx_hi = fmaxf(mx_hi, fmaxf(sacc[n][2], sacc[n][3]));
        }
#pragma unroll
        for (int off = 1; off <= 2; off <<= 1) {
            mx_lo = fmaxf(mx_lo, __shfl_xor_sync(0xffffffffu, mx_lo, off));
            mx_hi = fmaxf(mx_hi, __shfl_xor_sync(0xffffffffu, mx_hi, off));
        }
        float mn_lo = fmaxf(m_lo, mx_lo);
        float mn_hi = fmaxf(m_hi, mx_hi);
        float sum_lo = 0.f, sum_hi = 0.f;
#pragma unroll
        for (int n = 0; n < 8; n++) {
            sacc[n][0] = expf(sacc[n][0] - mn_lo);
            sacc[n][1] = expf(sacc[n][1] - mn_lo);
            sacc[n][2] = expf(sacc[n][2] - mn_hi);
            sacc[n][3] = expf(sacc[n][3] - mn_hi);
            sum_lo += sacc[n][0] + sacc[n][1];
            sum_hi += sacc[n][2] + sacc[n][3];
        }
#pragma unroll
        for (int off = 1; off <= 2; off <<= 1) {
            sum_lo += __shfl_xor_sync(0xffffffffu, sum_lo, off);
            sum_hi += __shfl_xor_sync(0xffffffffu, sum_hi, off);
        }
        float al_lo = expf(m_lo - mn_lo);
        float al_hi = expf(m_hi - mn_hi);
        l_lo = l_lo * al_lo + sum_lo;  m_lo = mn_lo;
        l_hi = l_hi * al_hi + sum_hi;  m_hi = mn_hi;
#pragma unroll
        for (int g = 0; g < 16; g++) {
            acc[g][0] *= al_lo; acc[g][1] *= al_lo;
            acc[g][2] *= al_hi; acc[g][3] *= al_hi;
        }

        // ---- pack P fragments ----
        uint32_t pf[4][4];
#pragma unroll
        for (int j = 0; j < 4; j++) {
            __half2 p0 = __floats2half2_rn(sacc[2*j][0],   sacc[2*j][1]);
            __half2 p1 = __floats2half2_rn(sacc[2*j][2],   sacc[2*j][3]);
            __half2 p2 = __floats2half2_rn(sacc[2*j+1][0], sacc[2*j+1][1]);
            __half2 p3 = __floats2half2_rn(sacc[2*j+1][2], sacc[2*j+1][3]);
            pf[j][0] = *(uint32_t*)&p0;
            pf[j][1] = *(uint32_t*)&p1;
            pf[j][2] = *(uint32_t*)&p2;
            pf[j][3] = *(uint32_t*)&p3;
        }

        // ---- O += P @ V ----
        int vrow_off = (lane & 7) + ((lane >> 3) & 1) * 8;
#pragma unroll
        for (int j = 0; j < 4; j++) {
            int c0 = j * 16;
#pragma unroll
            for (int g = 0; g < 8; g++) {
                uint32_t vf[4];
                ldsm_x4_t(vf, fl_addr(sV, c0 + vrow_off, 2 * g + lch));
                uint32_t b0[2] = {vf[0], vf[1]};
                uint32_t b1[2] = {vf[2], vf[3]};
                mma16816(acc[2 * g],     pf[j], b0);
                mma16816(acc[2 * g + 1], pf[j], b1);
            }
        }
        __syncthreads();
    }

    // ---- epilogue: single fp16 output ----
    float inv_lo = 1.f / l_lo, inv_hi = 1.f / l_hi;
    int r_lo = qt0 + m0 + (lane >> 2);
    int r_hi = r_lo + 8;
    size_t base_lo = (size_t)(b * TT + r_lo) * NQ + h * HD;
    size_t base_hi = (size_t)(b * TT + r_hi) * NQ + h * HD;
#pragma unroll
    for (int g = 0; g < 16; g++) {
        int d = g * 8 + (lane & 3) * 2;
        *(__half2*)&O[base_lo + d] = __floats2half2_rn(acc[g][0] * inv_lo, acc[g][1] * inv_lo);
        *(__half2*)&O[base_hi + d] = __floats2half2_rn(acc[g][2] * inv_hi, acc[g][3] * inv_hi);
    }
}

// ---------------- launch ----------------
extern "C" void kernel_launch(void* const* d_in, const int* in_sizes, int n_in,
                              void* d_out, int out_size)
{
    const float* x   = (const float*)d_in[0];
    const float* wq  = (const float*)d_in[1];
    const float* wk  = (const float*)d_in[2];
    const float* wv  = (const float*)d_in[3];
    const float* wo  = (const float*)d_in[4];
    const float* qnw = (const float*)d_in[5];
    const float* knw = (const float*)d_in[6];
    float* out = (float*)d_out;

    __half *x16, *wqt, *wkt, *wvt, *wot, *a16, *q16, *k16, *v16;
    float *qb, *kb;
    cudaGetSymbolAddress((void**)&x16, g_x16);
    cudaGetSymbolAddress((void**)&wqt, g_wqt); cudaGetSymbolAddress((void**)&wkt, g_wkt);
    cudaGetSymbolAddress((void**)&wvt, g_wvt); cudaGetSymbolAddress((void**)&wot, g_wot);
    cudaGetSymbolAddress((void**)&a16, g_attn16);
    cudaGetSymbolAddress((void**)&qb, g_q);    cudaGetSymbolAddress((void**)&kb, g_k);
    cudaGetSymbolAddress((void**)&q16, g_q16); cudaGetSymbolAddress((void**)&k16, g_k16);
    cudaGetSymbolAddress((void**)&v16, g_v16);

    // convert x to fp16, transpose weights to fp16 [N,K]
    convert_f16_kernel<<<(MROWS * HID + 255) / 256, 256>>>(x, x16, MROWS * HID);
    transpose_f16_kernel<<<dim3(NQ / 32, HID / 32), dim3(32, 8)>>>(wq, wqt, HID, NQ);
    transpose_f16_kernel<<<dim3(NKVD / 32, HID / 32), dim3(32, 8)>>>(wk, wkt, HID, NKVD);
    transpose_f16_kernel<<<dim3(NKVD / 32, HID / 32), dim3(32, 8)>>>(wv, wvt, HID, NKVD);
    transpose_f16_kernel<<<dim3(HID / 32, NQ / 32), dim3(32, 8)>>>(wo, wot, NQ, HID);

    cudaFuncSetAttribute(gemm_f16_kernel<float>,
                         cudaFuncAttributeMaxDynamicSharedMemorySize, GEMM_SMEM);
    cudaFuncSetAttribute(gemm_f16_kernel<__half>,
                         cudaFuncAttributeMaxDynamicSharedMemorySize, GEMM_SMEM);

    // QKV projections (single-term fp16)
    gemm_f16_kernel<float><<<dim3(NQ / GEMM_BN, MROWS / GEMM_BM), GEMM_THREADS, GEMM_SMEM>>>(
        x16, wqt, qb, MROWS, NQ, HID);
    gemm_f16_kernel<float><<<dim3(NKVD / GEMM_BN, MROWS / GEMM_BM), GEMM_THREADS, GEMM_SMEM>>>(
        x16, wkt, kb, MROWS, NKVD, HID);
    gemm_f16_kernel<__half><<<dim3(NKVD / GEMM_BN, MROWS / GEMM_BM), GEMM_THREADS, GEMM_SMEM>>>(
        x16, wvt, v16, MROWS, NKVD, HID);

    // per-head RMSNorm + RoPE -> fp16 (Q pre-scaled by 1/sqrt(HD))
    rmsnorm_rope_f16_kernel<<<MROWS * NH, 128>>>(qb, qnw, q16, NH, 0.08838834764831845f);
    rmsnorm_rope_f16_kernel<<<MROWS * NKV, 128>>>(kb, knw, k16, NKV, 1.0f);

    // flash attention (fp16 in/out, pipelined K/V)
    cudaFuncSetAttribute(flash16_kernel, cudaFuncAttributeMaxDynamicSharedMemorySize, FL_SMEM);
    flash16_kernel<<<dim3(TT / 64, NH, BB), 128, FL_SMEM>>>(q16, k16, v16, a16);

    // output projection (single-term fp16, fp32 out)
    gemm_f16_kernel<float><<<dim3(HID / GEMM_BN, MROWS / GEMM_BM), GEMM_THREADS, GEMM_SMEM>>>(
        a16, wot, out, MROWS, HID, NQ);
}